// round 2
// baseline (speedup 1.0000x reference)
#include <cuda_runtime.h>
#include <cuda_bf16.h>
#include <math.h>

// Problem constants
#define BB 4
#define NN 2048
#define CC 512
#define HH 8
#define DD 64
#define TT (BB*NN)          // 8192 tokens
#define FF 2048             // d_ff

// ---------------------------------------------------------------------------
// Scratch: one big __device__ array (no runtime allocation allowed)
// Layout (float offsets):
//   xn    @ 0          (TT*CC)
//   en    @ 4194304    (TT*CC)
//   qkv   @ 8388608    (TT*3CC)
//   s     @ 20971520   (TT*CC)
//   gate  @ 25165824   (TT*CC)
//   att   @ 29360128   (TT*CC)
//   x1    @ 33554432   (TT*CC)
//   xn3   @ 37748736   (TT*CC)
//   h     @ 41943040   (TT*FF)
// total 58720256 floats (~224 MB)
#define OFF_XN   0ull
#define OFF_EN   4194304ull
#define OFF_QKV  8388608ull
#define OFF_S    20971520ull
#define OFF_GATE 25165824ull
#define OFF_ATT  29360128ull
#define OFF_X1   33554432ull
#define OFF_XN3  37748736ull
#define OFF_H    41943040ull
#define SCRATCH_FLOATS 58720256ull

__device__ float g_scratch[SCRATCH_FLOATS];

// ---------------------------------------------------------------------------
// LayerNorm: one block per row of 512 floats, 128 threads, float4 per thread.
__global__ void ln_kernel(const float* __restrict__ x,
                          const float* __restrict__ w,
                          const float* __restrict__ b,
                          float* __restrict__ y) {
    int row = blockIdx.x;
    int tid = threadIdx.x;                 // 0..127
    const float4* xr = (const float4*)(x + (size_t)row * CC);
    float4 v = xr[tid];
    float s  = v.x + v.y + v.z + v.w;
    float ss = v.x*v.x + v.y*v.y + v.z*v.z + v.w*v.w;
    #pragma unroll
    for (int off = 16; off; off >>= 1) {
        s  += __shfl_xor_sync(0xffffffffu, s,  off);
        ss += __shfl_xor_sync(0xffffffffu, ss, off);
    }
    __shared__ float sm[4], sm2[4];
    int warp = tid >> 5, lane = tid & 31;
    if (lane == 0) { sm[warp] = s; sm2[warp] = ss; }
    __syncthreads();
    float tot  = sm[0] + sm[1] + sm[2] + sm[3];
    float tot2 = sm2[0] + sm2[1] + sm2[2] + sm2[3];
    float mu   = tot * (1.0f / CC);
    float var  = tot2 * (1.0f / CC) - mu * mu;
    float rstd = rsqrtf(var + 1e-5f);
    float4 wv = ((const float4*)w)[tid];
    float4 bv = ((const float4*)b)[tid];
    float4 o;
    o.x = (v.x - mu) * rstd * wv.x + bv.x;
    o.y = (v.y - mu) * rstd * wv.y + bv.y;
    o.z = (v.z - mu) * rstd * wv.z + bv.z;
    o.w = (v.w - mu) * rstd * wv.w + bv.w;
    ((float4*)(y + (size_t)row * CC))[tid] = o;
}

// ---------------------------------------------------------------------------
// Tiled SGEMM: C[M,N] = op(A[M,K] (* A2) @ B[K,N] + bias) + res
// BM=BN=64, BK=16, 256 threads, 4x4 per-thread register tile.
// act: 0 = none, 1 = exact-erf GELU (applied after bias, before residual add).
__global__ void __launch_bounds__(256) sgemm_kernel(
    const float* __restrict__ A, const float* __restrict__ A2,
    const float* __restrict__ B, const float* __restrict__ bias,
    const float* __restrict__ res, float* __restrict__ C,
    int M, int N, int K, int act)
{
    __shared__ float As[16][65];   // transposed A tile, padded
    __shared__ float Bs[16][64];

    int tid = threadIdx.x;
    int tx = tid & 15, ty = tid >> 4;
    int m0 = blockIdx.y * 64, n0 = blockIdx.x * 64;

    int la_r = tid >> 2;            // 0..63 : row within A tile
    int la_c = (tid & 3) * 4;       // 0,4,8,12 : col (k) within A tile
    int lb_r = tid >> 4;            // 0..15 : row (k) within B tile
    int lb_c = (tid & 15) * 4;      // col within B tile

    float acc[4][4];
    #pragma unroll
    for (int i = 0; i < 4; i++)
        #pragma unroll
        for (int j = 0; j < 4; j++) acc[i][j] = 0.f;

    for (int k0 = 0; k0 < K; k0 += 16) {
        float4 a4 = *(const float4*)&A[(size_t)(m0 + la_r) * K + k0 + la_c];
        if (A2) {
            float4 a2 = *(const float4*)&A2[(size_t)(m0 + la_r) * K + k0 + la_c];
            a4.x *= a2.x; a4.y *= a2.y; a4.z *= a2.z; a4.w *= a2.w;
        }
        As[la_c + 0][la_r] = a4.x;
        As[la_c + 1][la_r] = a4.y;
        As[la_c + 2][la_r] = a4.z;
        As[la_c + 3][la_r] = a4.w;
        float4 b4 = *(const float4*)&B[(size_t)(k0 + lb_r) * N + n0 + lb_c];
        *(float4*)&Bs[lb_r][lb_c] = b4;
        __syncthreads();

        #pragma unroll
        for (int kk = 0; kk < 16; kk++) {
            float av[4], bv[4];
            #pragma unroll
            for (int i = 0; i < 4; i++) av[i] = As[kk][ty * 4 + i];
            #pragma unroll
            for (int j = 0; j < 4; j++) bv[j] = Bs[kk][tx * 4 + j];
            #pragma unroll
            for (int i = 0; i < 4; i++)
                #pragma unroll
                for (int j = 0; j < 4; j++)
                    acc[i][j] += av[i] * bv[j];
        }
        __syncthreads();
    }

    #pragma unroll
    for (int i = 0; i < 4; i++) {
        int m = m0 + ty * 4 + i;
        #pragma unroll
        for (int j = 0; j < 4; j++) {
            int n = n0 + tx * 4 + j;
            float v = acc[i][j];
            if (bias) v += bias[n];
            if (act == 1) v = 0.5f * v * (1.0f + erff(v * 0.70710678118654752f));
            if (res) v += res[(size_t)m * N + n];
            C[(size_t)m * N + n] = v;
        }
    }
}

// ---------------------------------------------------------------------------
// Flash attention, fp32. One block = 64 query rows for one (b,h).
// q = qkv[t, h*64+d]; k = qkv[t, 512 + h*64+d] + s[t, h*64+d]; v = qkv[t, 1024 + h*64+d]
// out[t, h*64+d] = softmax(q (k+s)^T * 0.125) @ v
__global__ void __launch_bounds__(256) attn_kernel(
    const float* __restrict__ qkv, const float* __restrict__ sb,
    float* __restrict__ out)
{
    __shared__ float q_s[64][64];
    __shared__ float kT_s[64][64];   // [d][j ^ (d&31)]  (xor swizzle)
    __shared__ float v_s[64][64];    // [j][d]

    int tid  = threadIdx.x;
    int lane = tid & 31, warp = tid >> 5;
    int qt = blockIdx.x, h = blockIdx.y, b = blockIdx.z;
    int tq0 = b * NN + qt * 64;
    int hcol = h * DD;

    for (int idx = tid; idx < 4096; idx += 256) {
        int r = idx >> 6, d = idx & 63;
        q_s[r][d] = qkv[(size_t)(tq0 + r) * (3 * CC) + hcol + d];
    }

    float m[8], l[8], o0[8], o1[8];
    #pragma unroll
    for (int r = 0; r < 8; r++) { m[r] = -1e30f; l[r] = 0.f; o0[r] = 0.f; o1[r] = 0.f; }
    int r0 = warp * 8;

    for (int kt = 0; kt < NN / 64; kt++) {
        int tk0 = b * NN + kt * 64;
        for (int idx = tid; idx < 4096; idx += 256) {
            int j = idx >> 6, d = idx & 63;
            size_t trow = (size_t)(tk0 + j);
            float kv = qkv[trow * (3 * CC) + CC + hcol + d] + sb[trow * CC + hcol + d];
            kT_s[d][j ^ (d & 31)] = kv;
            v_s[j][d] = qkv[trow * (3 * CC) + 2 * CC + hcol + d];
        }
        __syncthreads();

        float s0[8], s1[8];
        #pragma unroll
        for (int r = 0; r < 8; r++) { s0[r] = 0.f; s1[r] = 0.f; }

        #pragma unroll 8
        for (int d = 0; d < 64; d++) {
            int c = lane ^ (d & 31);
            float k0v = kT_s[d][c];
            float k1v = kT_s[d][c + 32];
            #pragma unroll
            for (int r = 0; r < 8; r++) {
                float qv = q_s[r0 + r][d];
                s0[r] += qv * k0v;
                s1[r] += qv * k1v;
            }
        }

        #pragma unroll
        for (int r = 0; r < 8; r++) {
            float sc0 = s0[r] * 0.125f, sc1 = s1[r] * 0.125f;
            float tm = fmaxf(sc0, sc1);
            #pragma unroll
            for (int off = 16; off; off >>= 1)
                tm = fmaxf(tm, __shfl_xor_sync(0xffffffffu, tm, off));
            float mn   = fmaxf(m[r], tm);
            float corr = __expf(m[r] - mn);
            float p0 = __expf(sc0 - mn), p1 = __expf(sc1 - mn);
            float ps = p0 + p1;
            #pragma unroll
            for (int off = 16; off; off >>= 1)
                ps += __shfl_xor_sync(0xffffffffu, ps, off);
            l[r] = l[r] * corr + ps;
            m[r] = mn;
            o0[r] *= corr; o1[r] *= corr;
            s0[r] = p0; s1[r] = p1;      // reuse as probabilities
        }

        #pragma unroll 4
        for (int j = 0; j < 32; j++) {
            float va0 = v_s[j][lane],      va1 = v_s[j][lane + 32];
            float vb0 = v_s[j + 32][lane], vb1 = v_s[j + 32][lane + 32];
            #pragma unroll
            for (int r = 0; r < 8; r++) {
                float pa = __shfl_sync(0xffffffffu, s0[r], j);
                float pb = __shfl_sync(0xffffffffu, s1[r], j);
                o0[r] += pa * va0 + pb * vb0;
                o1[r] += pa * va1 + pb * vb1;
            }
        }
        __syncthreads();
    }

    #pragma unroll
    for (int r = 0; r < 8; r++) {
        float inv = 1.0f / l[r];
        size_t t = (size_t)(tq0 + r0 + r);
        out[t * CC + hcol + lane]      = o0[r] * inv;
        out[t * CC + hcol + lane + 32] = o1[r] * inv;
    }
}

// ---------------------------------------------------------------------------
extern "C" void kernel_launch(void* const* d_in, const int* in_sizes, int n_in,
                              void* d_out, int out_size) {
    const float* x      = (const float*)d_in[0];
    const float* e      = (const float*)d_in[1];
    const float* w_qkv  = (const float*)d_in[2];
    const float* w_s    = (const float*)d_in[3];
    const float* w_gate = (const float*)d_in[4];
    const float* w_proj = (const float*)d_in[5];
    const float* b_proj = (const float*)d_in[6];
    const float* ln1_w  = (const float*)d_in[7];
    const float* ln1_b  = (const float*)d_in[8];
    const float* ln2_w  = (const float*)d_in[9];
    const float* ln2_b  = (const float*)d_in[10];
    const float* ln3_w  = (const float*)d_in[11];
    const float* ln3_b  = (const float*)d_in[12];
    const float* w_fc1  = (const float*)d_in[13];
    const float* b_fc1  = (const float*)d_in[14];
    const float* w_fc2  = (const float*)d_in[15];
    const float* b_fc2  = (const float*)d_in[16];
    float* out = (float*)d_out;

    void* scr_v = nullptr;
    cudaGetSymbolAddress(&scr_v, g_scratch);
    float* scr = (float*)scr_v;
    float* g_xn   = scr + OFF_XN;
    float* g_en   = scr + OFF_EN;
    float* g_qkv  = scr + OFF_QKV;
    float* g_s    = scr + OFF_S;
    float* g_gate = scr + OFF_GATE;
    float* g_att  = scr + OFF_ATT;
    float* g_x1   = scr + OFF_X1;
    float* g_xn3  = scr + OFF_XN3;
    float* g_h    = scr + OFF_H;

    // LN1(x), LN2(e)
    ln_kernel<<<TT, 128>>>(x, ln1_w, ln1_b, g_xn);
    ln_kernel<<<TT, 128>>>(e, ln2_w, ln2_b, g_en);

    // qkv = xn @ w_qkv ; s = en @ w_s ; gate = xn @ w_gate
    sgemm_kernel<<<dim3(3 * CC / 64, TT / 64), 256>>>(
        g_xn, nullptr, w_qkv, nullptr, nullptr, g_qkv, TT, 3 * CC, CC, 0);
    sgemm_kernel<<<dim3(CC / 64, TT / 64), 256>>>(
        g_en, nullptr, w_s, nullptr, nullptr, g_s, TT, CC, CC, 0);
    sgemm_kernel<<<dim3(CC / 64, TT / 64), 256>>>(
        g_xn, nullptr, w_gate, nullptr, nullptr, g_gate, TT, CC, CC, 0);

    // attention
    attn_kernel<<<dim3(NN / 64, HH, BB), 256>>>(g_qkv, g_s, g_att);

    // x1 = x + (att * gate) @ w_proj + b_proj
    sgemm_kernel<<<dim3(CC / 64, TT / 64), 256>>>(
        g_att, g_gate, w_proj, b_proj, x, g_x1, TT, CC, CC, 0);

    // LN3(x1)
    ln_kernel<<<TT, 128>>>(g_x1, ln3_w, ln3_b, g_xn3);

    // h = gelu(xn3 @ w_fc1 + b_fc1)
    sgemm_kernel<<<dim3(FF / 64, TT / 64), 256>>>(
        g_xn3, nullptr, w_fc1, b_fc1, nullptr, g_h, TT, FF, CC, 1);

    // out = x1 + h @ w_fc2 + b_fc2
    sgemm_kernel<<<dim3(CC / 64, TT / 64), 256>>>(
        g_h, nullptr, w_fc2, b_fc2, g_x1, out, TT, CC, FF, 0);
}

// round 4
// speedup vs baseline: 1.8424x; 1.8424x over previous
#include <cuda_runtime.h>
#include <cuda_bf16.h>
#include <math.h>
#include <cstdint>

// Problem constants
#define BB 4
#define NN 2048
#define CC 512
#define HH 8
#define DD 64
#define TT (BB*NN)          // 8192 tokens
#define FF 2048             // d_ff

// ---------------------------------------------------------------------------
// Scratch layout (float units)
#define OFF_QKV   0ull           // fp32 [TT, 3C]
#define OFF_S     12582912ull    // fp32 [TT, C]
#define OFF_GATE  16777216ull    // fp32 [TT, C]
#define OFF_ATT   20971520ull    // fp32 [TT, C]
#define OFF_X1    25165824ull    // fp32 [TT, C]
#define OFF_XNB   29360128ull    // bf16 [TT, C]
#define OFF_ENB   31457280ull    // bf16 [TT, C]
#define OFF_XN3B  33554432ull    // bf16 [TT, C]
#define OFF_AGB   35651584ull    // bf16 [TT, C]
#define OFF_HB    37748736ull    // bf16 [TT, FF]
#define OFF_WQKVT 46137344ull    // bf16 [3C, C]
#define OFF_WST   46530560ull    // bf16 [C, C]
#define OFF_WGT   46661632ull    // bf16 [C, C]
#define OFF_WPT   46792704ull    // bf16 [C, C]
#define OFF_WF1T  46923776ull    // bf16 [FF, C]
#define OFF_WF2T  47448064ull    // bf16 [C, FF]
#define SCRATCH_FLOATS 47972352ull

__device__ float g_scratch[SCRATCH_FLOATS];

// ---------------------------------------------------------------------------
__device__ __forceinline__ uint32_t smem_u32(const void* p) {
    uint32_t a;
    asm("{ .reg .u64 t; cvta.to.shared.u64 t, %1; cvt.u32.u64 %0, t; }" : "=r"(a) : "l"(p));
    return a;
}
__device__ __forceinline__ void cp_async16(uint32_t saddr, const void* gaddr) {
    asm volatile("cp.async.cg.shared.global [%0], [%1], 16;" :: "r"(saddr), "l"(gaddr) : "memory");
}
__device__ __forceinline__ void cp_commit() {
    asm volatile("cp.async.commit_group;" ::: "memory");
}
__device__ __forceinline__ void ldmx4(uint32_t& r0, uint32_t& r1, uint32_t& r2, uint32_t& r3,
                                      uint32_t addr) {
    asm volatile("ldmatrix.sync.aligned.m8n8.x4.shared.b16 {%0,%1,%2,%3}, [%4];"
                 : "=r"(r0), "=r"(r1), "=r"(r2), "=r"(r3) : "r"(addr));
}
__device__ __forceinline__ void mma16816(float* c, const uint32_t* a, uint32_t b0, uint32_t b1) {
    asm volatile(
        "mma.sync.aligned.m16n8k16.row.col.f32.bf16.bf16.f32 "
        "{%0,%1,%2,%3}, {%4,%5,%6,%7}, {%8,%9}, {%0,%1,%2,%3};"
        : "+f"(c[0]), "+f"(c[1]), "+f"(c[2]), "+f"(c[3])
        : "r"(a[0]), "r"(a[1]), "r"(a[2]), "r"(a[3]), "r"(b0), "r"(b1));
}

// ---------------------------------------------------------------------------
// LayerNorm -> bf16 output
__global__ void ln_kernel(const float* __restrict__ x,
                          const float* __restrict__ w,
                          const float* __restrict__ b,
                          __nv_bfloat16* __restrict__ y) {
    int row = blockIdx.x;
    int tid = threadIdx.x;
    const float4* xr = (const float4*)(x + (size_t)row * CC);
    float4 v = xr[tid];
    float s  = v.x + v.y + v.z + v.w;
    float ss = v.x*v.x + v.y*v.y + v.z*v.z + v.w*v.w;
    #pragma unroll
    for (int off = 16; off; off >>= 1) {
        s  += __shfl_xor_sync(0xffffffffu, s,  off);
        ss += __shfl_xor_sync(0xffffffffu, ss, off);
    }
    __shared__ float sm[4], sm2[4];
    int warp = tid >> 5, lane = tid & 31;
    if (lane == 0) { sm[warp] = s; sm2[warp] = ss; }
    __syncthreads();
    float tot  = sm[0] + sm[1] + sm[2] + sm[3];
    float tot2 = sm2[0] + sm2[1] + sm2[2] + sm2[3];
    float mu   = tot * (1.0f / CC);
    float var  = tot2 * (1.0f / CC) - mu * mu;
    float rstd = rsqrtf(var + 1e-5f);
    float4 wv = ((const float4*)w)[tid];
    float4 bv = ((const float4*)b)[tid];
    __nv_bfloat162 p0 = __floats2bfloat162_rn((v.x - mu) * rstd * wv.x + bv.x,
                                              (v.y - mu) * rstd * wv.y + bv.y);
    __nv_bfloat162 p1 = __floats2bfloat162_rn((v.z - mu) * rstd * wv.z + bv.z,
                                              (v.w - mu) * rstd * wv.w + bv.w);
    uint2 o;
    o.x = *(uint32_t*)&p0;
    o.y = *(uint32_t*)&p1;
    ((uint2*)(y + (size_t)row * CC))[tid] = o;
}

// ---------------------------------------------------------------------------
// Weight transpose + fp32->bf16: W[K,N] -> WT[N,K]
__global__ void wt_kernel(const float* __restrict__ W, __nv_bfloat16* __restrict__ WT,
                          int K, int N) {
    __shared__ float t[32][33];
    int k0 = blockIdx.y * 32, n0 = blockIdx.x * 32;
    int tx = threadIdx.x, ty = threadIdx.y;   // 32 x 8
    #pragma unroll
    for (int i = 0; i < 32; i += 8)
        t[ty + i][tx] = W[(size_t)(k0 + ty + i) * N + n0 + tx];
    __syncthreads();
    #pragma unroll
    for (int i = 0; i < 32; i += 8)
        WT[(size_t)(n0 + ty + i) * K + k0 + tx] = __float2bfloat16(t[tx][ty + i]);
}

// ---------------------------------------------------------------------------
// Elementwise: out_bf16 = a * b
__global__ void mulcvt_kernel(const float* __restrict__ a, const float* __restrict__ b,
                              __nv_bfloat16* __restrict__ o) {
    int i = blockIdx.x * 256 + threadIdx.x;
    float4 av = ((const float4*)a)[i];
    float4 bv = ((const float4*)b)[i];
    __nv_bfloat162 p0 = __floats2bfloat162_rn(av.x * bv.x, av.y * bv.y);
    __nv_bfloat162 p1 = __floats2bfloat162_rn(av.z * bv.z, av.w * bv.w);
    uint2 u;
    u.x = *(uint32_t*)&p0;
    u.y = *(uint32_t*)&p1;
    ((uint2*)o)[i] = u;
}

// ---------------------------------------------------------------------------
// HMMA bf16 GEMM: C[M,N] = act(A[M,K] @ Bt[N,K]^T + bias) + res
// 128x128 CTA tile, BK=32, 8 warps (4 along M x 2 along N), warp tile 32x64.
// Smem rows: 32 bf16 = 64B data, stride 80B (conflict-free ldmatrix).
#define MMROW 80
#define MMBUF (128 * MMROW)          // 10240 B per operand tile
#define MMSTG (2 * MMBUF)            // A + B per stage

template<int ACT, bool OUT_BF16>
__global__ void __launch_bounds__(256) mm_kernel(
    const __nv_bfloat16* __restrict__ A,   // [M,K]
    const __nv_bfloat16* __restrict__ Bt,  // [N,K]
    const float* __restrict__ bias,        // [N] or null
    const float* __restrict__ res,         // [M,N] or null
    void* __restrict__ Cout,
    int M, int N, int K)
{
    __shared__ __align__(16) char smem[2 * MMSTG];
    uint32_t sb = smem_u32(smem);

    int tid = threadIdx.x, wid = tid >> 5, lane = tid & 31;
    int m0 = blockIdx.y * 128, n0 = blockIdx.x * 128;
    int wm = wid & 3, wn = wid >> 2;          // warp coords: 4 x 2

    // loader mapping: thread covers 2 rows per operand, 16B chunk each
    int lr = tid >> 2;            // 0..63
    int lc = (tid & 3) * 16;      // byte offset in 64B row

    const char* Abase = (const char*)A;
    const char* Bbase = (const char*)Bt;
    size_t rstride = (size_t)K * 2;

    int KC = K >> 5;   // BK = 32

    auto load_tile = [&](int stg, int kc) {
        uint32_t sa = sb + stg * MMSTG;
        uint32_t sB = sa + MMBUF;
        size_t koff = (size_t)kc * 64;
        #pragma unroll
        for (int i = 0; i < 2; i++) {
            int r = lr + i * 64;
            cp_async16(sa + r * MMROW + lc,
                       Abase + (size_t)(m0 + r) * rstride + koff + lc);
            cp_async16(sB + r * MMROW + lc,
                       Bbase + (size_t)(n0 + r) * rstride + koff + lc);
        }
        cp_commit();
    };

    float acc[2][8][4];
    #pragma unroll
    for (int mi = 0; mi < 2; mi++)
        #pragma unroll
        for (int ni = 0; ni < 8; ni++)
            #pragma unroll
            for (int j = 0; j < 4; j++) acc[mi][ni][j] = 0.f;

    load_tile(0, 0);

    // ldmatrix lane addressing (common to A and B)
    uint32_t lrow16 = (lane & 15);
    uint32_t lkhalf = (lane >> 4) * 16;      // bytes: 8 bf16

    for (int kc = 0; kc < KC; kc++) {
        int stg = kc & 1;
        if (kc + 1 < KC) {
            load_tile(stg ^ 1, kc + 1);
            asm volatile("cp.async.wait_group 1;" ::: "memory");
        } else {
            asm volatile("cp.async.wait_group 0;" ::: "memory");
        }
        __syncthreads();

        uint32_t sA = sb + stg * MMSTG + (wm * 32 + lrow16) * MMROW + lkhalf;
        uint32_t sB = sb + stg * MMSTG + MMBUF + (wn * 64 + lrow16) * MMROW + lkhalf;

        #pragma unroll
        for (int ks = 0; ks < 2; ks++) {
            uint32_t koff = ks * 32;   // 16 bf16 = 32 bytes
            uint32_t a[2][4];
            #pragma unroll
            for (int mi = 0; mi < 2; mi++)
                ldmx4(a[mi][0], a[mi][1], a[mi][2], a[mi][3],
                      sA + mi * 16 * MMROW + koff);
            uint32_t b[4][4];
            #pragma unroll
            for (int nb = 0; nb < 4; nb++)
                ldmx4(b[nb][0], b[nb][1], b[nb][2], b[nb][3],
                      sB + nb * 16 * MMROW + koff);
            #pragma unroll
            for (int mi = 0; mi < 2; mi++)
                #pragma unroll
                for (int nb = 0; nb < 4; nb++) {
                    mma16816(acc[mi][nb * 2 + 0], a[mi], b[nb][0], b[nb][2]);
                    mma16816(acc[mi][nb * 2 + 1], a[mi], b[nb][1], b[nb][3]);
                }
        }
        __syncthreads();
    }

    // Epilogue
    int mrow = m0 + wm * 32 + (lane >> 2);
    int ncol0 = n0 + wn * 64 + (lane & 3) * 2;
    #pragma unroll
    for (int mi = 0; mi < 2; mi++) {
        #pragma unroll
        for (int ni = 0; ni < 8; ni++) {
            int n = ncol0 + ni * 8;
            #pragma unroll
            for (int half = 0; half < 2; half++) {   // rows +0, +8
                int m = mrow + mi * 16 + half * 8;
                float v0 = acc[mi][ni][half * 2 + 0];
                float v1 = acc[mi][ni][half * 2 + 1];
                if (bias) { v0 += bias[n]; v1 += bias[n + 1]; }
                if (ACT == 1) {
                    v0 = 0.5f * v0 * (1.0f + erff(v0 * 0.70710678118654752f));
                    v1 = 0.5f * v1 * (1.0f + erff(v1 * 0.70710678118654752f));
                }
                if (res) {
                    const float* rp = res + (size_t)m * N + n;
                    v0 += rp[0]; v1 += rp[1];
                }
                if (OUT_BF16) {
                    __nv_bfloat162 p = __floats2bfloat162_rn(v0, v1);
                    *(uint32_t*)((__nv_bfloat16*)Cout + (size_t)m * N + n) = *(uint32_t*)&p;
                } else {
                    float2 p = make_float2(v0, v1);
                    *(float2*)((float*)Cout + (size_t)m * N + n) = p;
                }
            }
        }
    }
}

// ---------------------------------------------------------------------------
// Flash attention, fp32 (unchanged this round).
__global__ void __launch_bounds__(256) attn_kernel(
    const float* __restrict__ qkv, const float* __restrict__ sb,
    float* __restrict__ out)
{
    __shared__ float q_s[64][64];
    __shared__ float kT_s[64][64];
    __shared__ float v_s[64][64];

    int tid  = threadIdx.x;
    int lane = tid & 31, warp = tid >> 5;
    int qt = blockIdx.x, h = blockIdx.y, b = blockIdx.z;
    int tq0 = b * NN + qt * 64;
    int hcol = h * DD;

    for (int idx = tid; idx < 4096; idx += 256) {
        int r = idx >> 6, d = idx & 63;
        q_s[r][d] = qkv[(size_t)(tq0 + r) * (3 * CC) + hcol + d];
    }

    float m[8], l[8], o0[8], o1[8];
    #pragma unroll
    for (int r = 0; r < 8; r++) { m[r] = -1e30f; l[r] = 0.f; o0[r] = 0.f; o1[r] = 0.f; }
    int r0 = warp * 8;

    for (int kt = 0; kt < NN / 64; kt++) {
        int tk0 = b * NN + kt * 64;
        for (int idx = tid; idx < 4096; idx += 256) {
            int j = idx >> 6, d = idx & 63;
            size_t trow = (size_t)(tk0 + j);
            float kv = qkv[trow * (3 * CC) + CC + hcol + d] + sb[trow * CC + hcol + d];
            kT_s[d][j ^ (d & 31)] = kv;
            v_s[j][d] = qkv[trow * (3 * CC) + 2 * CC + hcol + d];
        }
        __syncthreads();

        float s0[8], s1[8];
        #pragma unroll
        for (int r = 0; r < 8; r++) { s0[r] = 0.f; s1[r] = 0.f; }

        #pragma unroll 8
        for (int d = 0; d < 64; d++) {
            int c = lane ^ (d & 31);
            float k0v = kT_s[d][c];
            float k1v = kT_s[d][c + 32];
            #pragma unroll
            for (int r = 0; r < 8; r++) {
                float qv = q_s[r0 + r][d];
                s0[r] += qv * k0v;
                s1[r] += qv * k1v;
            }
        }

        #pragma unroll
        for (int r = 0; r < 8; r++) {
            float sc0 = s0[r] * 0.125f, sc1 = s1[r] * 0.125f;
            float tm = fmaxf(sc0, sc1);
            #pragma unroll
            for (int off = 16; off; off >>= 1)
                tm = fmaxf(tm, __shfl_xor_sync(0xffffffffu, tm, off));
            float mn   = fmaxf(m[r], tm);
            float corr = __expf(m[r] - mn);
            float p0 = __expf(sc0 - mn), p1 = __expf(sc1 - mn);
            float ps = p0 + p1;
            #pragma unroll
            for (int off = 16; off; off >>= 1)
                ps += __shfl_xor_sync(0xffffffffu, ps, off);
            l[r] = l[r] * corr + ps;
            m[r] = mn;
            o0[r] *= corr; o1[r] *= corr;
            s0[r] = p0; s1[r] = p1;
        }

        #pragma unroll 4
        for (int j = 0; j < 32; j++) {
            float va0 = v_s[j][lane],      va1 = v_s[j][lane + 32];
            float vb0 = v_s[j + 32][lane], vb1 = v_s[j + 32][lane + 32];
            #pragma unroll
            for (int r = 0; r < 8; r++) {
                float pa = __shfl_sync(0xffffffffu, s0[r], j);
                float pb = __shfl_sync(0xffffffffu, s1[r], j);
                o0[r] += pa * va0 + pb * vb0;
                o1[r] += pa * va1 + pb * vb1;
            }
        }
        __syncthreads();
    }

    #pragma unroll
    for (int r = 0; r < 8; r++) {
        float inv = 1.0f / l[r];
        size_t t = (size_t)(tq0 + r0 + r);
        out[t * CC + hcol + lane]      = o0[r] * inv;
        out[t * CC + hcol + lane + 32] = o1[r] * inv;
    }
}

// ---------------------------------------------------------------------------
extern "C" void kernel_launch(void* const* d_in, const int* in_sizes, int n_in,
                              void* d_out, int out_size) {
    const float* x      = (const float*)d_in[0];
    const float* e      = (const float*)d_in[1];
    const float* w_qkv  = (const float*)d_in[2];
    const float* w_s    = (const float*)d_in[3];
    const float* w_gate = (const float*)d_in[4];
    const float* w_proj = (const float*)d_in[5];
    const float* b_proj = (const float*)d_in[6];
    const float* ln1_w  = (const float*)d_in[7];
    const float* ln1_b  = (const float*)d_in[8];
    const float* ln2_w  = (const float*)d_in[9];
    const float* ln2_b  = (const float*)d_in[10];
    const float* ln3_w  = (const float*)d_in[11];
    const float* ln3_b  = (const float*)d_in[12];
    const float* w_fc1  = (const float*)d_in[13];
    const float* b_fc1  = (const float*)d_in[14];
    const float* w_fc2  = (const float*)d_in[15];
    const float* b_fc2  = (const float*)d_in[16];
    float* out = (float*)d_out;

    void* scr_v = nullptr;
    cudaGetSymbolAddress(&scr_v, g_scratch);
    float* scr = (float*)scr_v;
    float*         g_qkv  = scr + OFF_QKV;
    float*         g_s    = scr + OFF_S;
    float*         g_gate = scr + OFF_GATE;
    float*         g_att  = scr + OFF_ATT;
    float*         g_x1   = scr + OFF_X1;
    __nv_bfloat16* g_xnb  = (__nv_bfloat16*)(scr + OFF_XNB);
    __nv_bfloat16* g_enb  = (__nv_bfloat16*)(scr + OFF_ENB);
    __nv_bfloat16* g_xn3b = (__nv_bfloat16*)(scr + OFF_XN3B);
    __nv_bfloat16* g_agb  = (__nv_bfloat16*)(scr + OFF_AGB);
    __nv_bfloat16* g_hb   = (__nv_bfloat16*)(scr + OFF_HB);
    __nv_bfloat16* wqkvT  = (__nv_bfloat16*)(scr + OFF_WQKVT);
    __nv_bfloat16* wsT    = (__nv_bfloat16*)(scr + OFF_WST);
    __nv_bfloat16* wgT    = (__nv_bfloat16*)(scr + OFF_WGT);
    __nv_bfloat16* wpT    = (__nv_bfloat16*)(scr + OFF_WPT);
    __nv_bfloat16* wf1T   = (__nv_bfloat16*)(scr + OFF_WF1T);
    __nv_bfloat16* wf2T   = (__nv_bfloat16*)(scr + OFF_WF2T);

    dim3 tb(32, 8);
    wt_kernel<<<dim3(3 * CC / 32, CC / 32), tb>>>(w_qkv, wqkvT, CC, 3 * CC);
    wt_kernel<<<dim3(CC / 32, CC / 32), tb>>>(w_s,    wsT,  CC, CC);
    wt_kernel<<<dim3(CC / 32, CC / 32), tb>>>(w_gate, wgT,  CC, CC);
    wt_kernel<<<dim3(CC / 32, CC / 32), tb>>>(w_proj, wpT,  CC, CC);
    wt_kernel<<<dim3(FF / 32, CC / 32), tb>>>(w_fc1,  wf1T, CC, FF);
    wt_kernel<<<dim3(CC / 32, FF / 32), tb>>>(w_fc2,  wf2T, FF, CC);

    ln_kernel<<<TT, 128>>>(x, ln1_w, ln1_b, g_xnb);
    ln_kernel<<<TT, 128>>>(e, ln2_w, ln2_b, g_enb);

    mm_kernel<0, false><<<dim3(3 * CC / 128, TT / 128), 256>>>(
        g_xnb, wqkvT, nullptr, nullptr, g_qkv, TT, 3 * CC, CC);
    mm_kernel<0, false><<<dim3(CC / 128, TT / 128), 256>>>(
        g_enb, wsT, nullptr, nullptr, g_s, TT, CC, CC);
    mm_kernel<0, false><<<dim3(CC / 128, TT / 128), 256>>>(
        g_xnb, wgT, nullptr, nullptr, g_gate, TT, CC, CC);

    attn_kernel<<<dim3(NN / 64, HH, BB), 256>>>(g_qkv, g_s, g_att);

    mulcvt_kernel<<<TT * CC / 4 / 256, 256>>>(g_att, g_gate, g_agb);

    mm_kernel<0, false><<<dim3(CC / 128, TT / 128), 256>>>(
        g_agb, wpT, b_proj, x, g_x1, TT, CC, CC);

    ln_kernel<<<TT, 128>>>(g_x1, ln3_w, ln3_b, g_xn3b);

    mm_kernel<1, true><<<dim3(FF / 128, TT / 128), 256>>>(
        g_xn3b, wf1T, b_fc1, nullptr, g_hb, TT, FF, CC);

    mm_kernel<0, false><<<dim3(CC / 128, TT / 128), 256>>>(
        g_hb, wf2T, b_fc2, g_x1, out, TT, CC, FF);
}

// round 6
// speedup vs baseline: 4.3992x; 2.3878x over previous
#include <cuda_runtime.h>
#include <cuda_bf16.h>
#include <math.h>
#include <cstdint>

// Problem constants
#define BB 4
#define NN 2048
#define CC 512
#define HH 8
#define DD 64
#define TT (BB*NN)          // 8192 tokens
#define FF 2048             // d_ff

// ---------------------------------------------------------------------------
// Scratch layout (float units)
#define OFF_QKV   0ull           // fp32 [TT, 3C]
#define OFF_S     12582912ull    // fp32 [TT, C]
#define OFF_GATE  16777216ull    // fp32 [TT, C]
#define OFF_ATT   20971520ull    // (unused now)
#define OFF_X1    25165824ull    // fp32 [TT, C]
#define OFF_XNB   29360128ull    // bf16 [TT, C]
#define OFF_ENB   31457280ull    // bf16 [TT, C]
#define OFF_XN3B  33554432ull    // bf16 [TT, C]
#define OFF_AGB   35651584ull    // bf16 [TT, C]
#define OFF_HB    37748736ull    // bf16 [TT, FF]
#define OFF_WQKVT 46137344ull    // bf16 [3C, C]
#define OFF_WST   46530560ull    // bf16 [C, C]
#define OFF_WGT   46661632ull    // bf16 [C, C]
#define OFF_WPT   46792704ull    // bf16 [C, C]
#define OFF_WF1T  46923776ull    // bf16 [FF, C]
#define OFF_WF2T  47448064ull    // bf16 [C, FF]
#define OFF_QH    47972352ull    // bf16 [B*H, N, 64]  (q * 0.125)
#define OFF_KH    50069504ull    // bf16 [B*H, N, 64]  (k + s)
#define OFF_VH    52166656ull    // bf16 [B*H, N, 64]
#define SCRATCH_FLOATS 54263808ull

__device__ float g_scratch[SCRATCH_FLOATS];

// ---------------------------------------------------------------------------
__device__ __forceinline__ uint32_t smem_u32(const void* p) {
    uint32_t a;
    asm("{ .reg .u64 t; cvta.to.shared.u64 t, %1; cvt.u32.u64 %0, t; }" : "=r"(a) : "l"(p));
    return a;
}
__device__ __forceinline__ void cp_async16(uint32_t saddr, const void* gaddr) {
    asm volatile("cp.async.cg.shared.global [%0], [%1], 16;" :: "r"(saddr), "l"(gaddr) : "memory");
}
__device__ __forceinline__ void cp_commit() {
    asm volatile("cp.async.commit_group;" ::: "memory");
}
__device__ __forceinline__ void ldmx4(uint32_t& r0, uint32_t& r1, uint32_t& r2, uint32_t& r3,
                                      uint32_t addr) {
    asm volatile("ldmatrix.sync.aligned.m8n8.x4.shared.b16 {%0,%1,%2,%3}, [%4];"
                 : "=r"(r0), "=r"(r1), "=r"(r2), "=r"(r3) : "r"(addr));
}
__device__ __forceinline__ void ldmx4t(uint32_t& r0, uint32_t& r1, uint32_t& r2, uint32_t& r3,
                                       uint32_t addr) {
    asm volatile("ldmatrix.sync.aligned.m8n8.x4.trans.shared.b16 {%0,%1,%2,%3}, [%4];"
                 : "=r"(r0), "=r"(r1), "=r"(r2), "=r"(r3) : "r"(addr));
}
__device__ __forceinline__ void mma16816(float* c, const uint32_t* a, uint32_t b0, uint32_t b1) {
    asm volatile(
        "mma.sync.aligned.m16n8k16.row.col.f32.bf16.bf16.f32 "
        "{%0,%1,%2,%3}, {%4,%5,%6,%7}, {%8,%9}, {%0,%1,%2,%3};"
        : "+f"(c[0]), "+f"(c[1]), "+f"(c[2]), "+f"(c[3])
        : "r"(a[0]), "r"(a[1]), "r"(a[2]), "r"(a[3]), "r"(b0), "r"(b1));
}
__device__ __forceinline__ uint32_t pack_bf16(float a, float b) {
    __nv_bfloat162 p = __floats2bfloat162_rn(a, b);
    return *(uint32_t*)&p;
}

// ---------------------------------------------------------------------------
// LayerNorm -> bf16 output
__global__ void ln_kernel(const float* __restrict__ x,
                          const float* __restrict__ w,
                          const float* __restrict__ b,
                          __nv_bfloat16* __restrict__ y) {
    int row = blockIdx.x;
    int tid = threadIdx.x;
    const float4* xr = (const float4*)(x + (size_t)row * CC);
    float4 v = xr[tid];
    float s  = v.x + v.y + v.z + v.w;
    float ss = v.x*v.x + v.y*v.y + v.z*v.z + v.w*v.w;
    #pragma unroll
    for (int off = 16; off; off >>= 1) {
        s  += __shfl_xor_sync(0xffffffffu, s,  off);
        ss += __shfl_xor_sync(0xffffffffu, ss, off);
    }
    __shared__ float sm[4], sm2[4];
    int warp = tid >> 5, lane = tid & 31;
    if (lane == 0) { sm[warp] = s; sm2[warp] = ss; }
    __syncthreads();
    float tot  = sm[0] + sm[1] + sm[2] + sm[3];
    float tot2 = sm2[0] + sm2[1] + sm2[2] + sm2[3];
    float mu   = tot * (1.0f / CC);
    float var  = tot2 * (1.0f / CC) - mu * mu;
    float rstd = rsqrtf(var + 1e-5f);
    float4 wv = ((const float4*)w)[tid];
    float4 bv = ((const float4*)b)[tid];
    uint2 o;
    o.x = pack_bf16((v.x - mu) * rstd * wv.x + bv.x, (v.y - mu) * rstd * wv.y + bv.y);
    o.y = pack_bf16((v.z - mu) * rstd * wv.z + bv.z, (v.w - mu) * rstd * wv.w + bv.w);
    ((uint2*)(y + (size_t)row * CC))[tid] = o;
}

// ---------------------------------------------------------------------------
// Weight transpose + fp32->bf16: W[K,N] -> WT[N,K]
__global__ void wt_kernel(const float* __restrict__ W, __nv_bfloat16* __restrict__ WT,
                          int K, int N) {
    __shared__ float t[32][33];
    int k0 = blockIdx.y * 32, n0 = blockIdx.x * 32;
    int tx = threadIdx.x, ty = threadIdx.y;   // 32 x 8
    #pragma unroll
    for (int i = 0; i < 32; i += 8)
        t[ty + i][tx] = W[(size_t)(k0 + ty + i) * N + n0 + tx];
    __syncthreads();
    #pragma unroll
    for (int i = 0; i < 32; i += 8)
        WT[(size_t)(n0 + ty + i) * K + k0 + tx] = __float2bfloat16(t[tx][ty + i]);
}

// ---------------------------------------------------------------------------
// qkv/s -> per-head bf16 buffers: qh = q*0.125, kh = k+s, vh = v
// One block per token row; 256 threads handle 384 float4 chunks.
__global__ void __launch_bounds__(256) qkvprep_kernel(
    const float* __restrict__ qkv, const float* __restrict__ s,
    __nv_bfloat16* __restrict__ qh, __nv_bfloat16* __restrict__ kh,
    __nv_bfloat16* __restrict__ vh)
{
    int t = blockIdx.x;
    int b = t >> 11, n = t & (NN - 1);
    const float4* qrow = (const float4*)(qkv + (size_t)t * (3 * CC));
    const float4* srow = (const float4*)(s + (size_t)t * CC);
    for (int idx = threadIdx.x; idx < 384; idx += 256) {
        int which = idx >> 7;        // 0=q,1=k,2=v
        int i = idx & 127;           // float4 index within 512 floats
        int dglob = i * 4;
        int h = dglob >> 6, dloc = dglob & 63;
        float4 v = qrow[which * 128 + i];
        if (which == 0) { v.x *= 0.125f; v.y *= 0.125f; v.z *= 0.125f; v.w *= 0.125f; }
        else if (which == 1) {
            float4 sv = srow[i];
            v.x += sv.x; v.y += sv.y; v.z += sv.z; v.w += sv.w;
        }
        __nv_bfloat16* dst = (which == 0) ? qh : (which == 1) ? kh : vh;
        uint2 o;
        o.x = pack_bf16(v.x, v.y);
        o.y = pack_bf16(v.z, v.w);
        *(uint2*)(dst + (((size_t)(b * HH + h) * NN + n) << 6) + dloc) = o;
    }
}

// ---------------------------------------------------------------------------
// HMMA bf16 GEMM: C[M,N] = act(A[M,K] @ Bt[N,K]^T + bias) + res
#define MMROW 80
#define MMBUF (128 * MMROW)
#define MMSTG (2 * MMBUF)

template<int ACT, bool OUT_BF16>
__global__ void __launch_bounds__(256) mm_kernel(
    const __nv_bfloat16* __restrict__ A,
    const __nv_bfloat16* __restrict__ Bt,
    const float* __restrict__ bias,
    const float* __restrict__ res,
    void* __restrict__ Cout,
    int M, int N, int K)
{
    __shared__ __align__(16) char smem[2 * MMSTG];
    uint32_t sb = smem_u32(smem);

    int tid = threadIdx.x, wid = tid >> 5, lane = tid & 31;
    int m0 = blockIdx.y * 128, n0 = blockIdx.x * 128;
    int wm = wid & 3, wn = wid >> 2;

    int lr = tid >> 2;
    int lc = (tid & 3) * 16;

    const char* Abase = (const char*)A;
    const char* Bbase = (const char*)Bt;
    size_t rstride = (size_t)K * 2;

    int KC = K >> 5;

    auto load_tile = [&](int stg, int kc) {
        uint32_t sa = sb + stg * MMSTG;
        uint32_t sB = sa + MMBUF;
        size_t koff = (size_t)kc * 64;
        #pragma unroll
        for (int i = 0; i < 2; i++) {
            int r = lr + i * 64;
            cp_async16(sa + r * MMROW + lc,
                       Abase + (size_t)(m0 + r) * rstride + koff + lc);
            cp_async16(sB + r * MMROW + lc,
                       Bbase + (size_t)(n0 + r) * rstride + koff + lc);
        }
        cp_commit();
    };

    float acc[2][8][4];
    #pragma unroll
    for (int mi = 0; mi < 2; mi++)
        #pragma unroll
        for (int ni = 0; ni < 8; ni++)
            #pragma unroll
            for (int j = 0; j < 4; j++) acc[mi][ni][j] = 0.f;

    load_tile(0, 0);

    uint32_t lrow16 = (lane & 15);
    uint32_t lkhalf = (lane >> 4) * 16;

    for (int kc = 0; kc < KC; kc++) {
        int stg = kc & 1;
        if (kc + 1 < KC) {
            load_tile(stg ^ 1, kc + 1);
            asm volatile("cp.async.wait_group 1;" ::: "memory");
        } else {
            asm volatile("cp.async.wait_group 0;" ::: "memory");
        }
        __syncthreads();

        uint32_t sA = sb + stg * MMSTG + (wm * 32 + lrow16) * MMROW + lkhalf;
        uint32_t sB = sb + stg * MMSTG + MMBUF + (wn * 64 + lrow16) * MMROW + lkhalf;

        #pragma unroll
        for (int ks = 0; ks < 2; ks++) {
            uint32_t koff = ks * 32;
            uint32_t a[2][4];
            #pragma unroll
            for (int mi = 0; mi < 2; mi++)
                ldmx4(a[mi][0], a[mi][1], a[mi][2], a[mi][3],
                      sA + mi * 16 * MMROW + koff);
            uint32_t b[4][4];
            #pragma unroll
            for (int nb = 0; nb < 4; nb++)
                ldmx4(b[nb][0], b[nb][1], b[nb][2], b[nb][3],
                      sB + nb * 16 * MMROW + koff);
            #pragma unroll
            for (int mi = 0; mi < 2; mi++)
                #pragma unroll
                for (int nb = 0; nb < 4; nb++) {
                    mma16816(acc[mi][nb * 2 + 0], a[mi], b[nb][0], b[nb][2]);
                    mma16816(acc[mi][nb * 2 + 1], a[mi], b[nb][1], b[nb][3]);
                }
        }
        __syncthreads();
    }

    int mrow = m0 + wm * 32 + (lane >> 2);
    int ncol0 = n0 + wn * 64 + (lane & 3) * 2;
    #pragma unroll
    for (int mi = 0; mi < 2; mi++) {
        #pragma unroll
        for (int ni = 0; ni < 8; ni++) {
            int n = ncol0 + ni * 8;
            #pragma unroll
            for (int half = 0; half < 2; half++) {
                int m = mrow + mi * 16 + half * 8;
                float v0 = acc[mi][ni][half * 2 + 0];
                float v1 = acc[mi][ni][half * 2 + 1];
                if (bias) { v0 += bias[n]; v1 += bias[n + 1]; }
                if (ACT == 1) {
                    v0 = 0.5f * v0 * (1.0f + erff(v0 * 0.70710678118654752f));
                    v1 = 0.5f * v1 * (1.0f + erff(v1 * 0.70710678118654752f));
                }
                if (res) {
                    const float* rp = res + (size_t)m * N + n;
                    v0 += rp[0]; v1 += rp[1];
                }
                if (OUT_BF16) {
                    *(uint32_t*)((__nv_bfloat16*)Cout + (size_t)m * N + n) = pack_bf16(v0, v1);
                } else {
                    float2 p = make_float2(v0, v1);
                    *(float2*)((float*)Cout + (size_t)m * N + n) = p;
                }
            }
        }
    }
}

// ---------------------------------------------------------------------------
// bf16 HMMA flash attention, fused gate-multiply epilogue.
// Block: one (b,h), 128 q rows. 8 warps x 16 rows. K-tile = 64 keys.
// Scale folded into qh. Output: agb[tok][h*64+d] = bf16(o * gate).
// smem layout (dynamic): Q [128 x 144B] @0; stage s: K @18432+s*18432, V @+9216.
#define AT_QOFF 0
#define AT_ROW  144
#define AT_KV0  18432
#define AT_STG  18432
#define AT_SMEM (18432 + 2 * 18432)

__global__ void __launch_bounds__(256) attn_kernel(
    const __nv_bfloat16* __restrict__ qh,
    const __nv_bfloat16* __restrict__ kh,
    const __nv_bfloat16* __restrict__ vh,
    const float* __restrict__ gate,
    __nv_bfloat16* __restrict__ outb)
{
    extern __shared__ char smem[];
    uint32_t sb = smem_u32(smem);
    int tid = threadIdx.x, wid = tid >> 5, lane = tid & 31;
    int qt = blockIdx.x, h = blockIdx.y, b = blockIdx.z;
    int bh = b * HH + h;
    int tq0 = qt * 128;

    const char* Qg = (const char*)(qh + (((size_t)bh * NN + tq0) << 6));
    const char* Kg = (const char*)(kh + ((size_t)bh * NN << 6));
    const char* Vg = (const char*)(vh + ((size_t)bh * NN << 6));

    // Load Q tile (128 rows x 128B)
    for (int i = tid; i < 1024; i += 256) {
        int r = i >> 3, c = (i & 7) * 16;
        cp_async16(sb + AT_QOFF + r * AT_ROW + c, Qg + (size_t)r * 128 + c);
    }
    cp_commit();

    auto loadKV = [&](int kt, int stg) {
        const char* K0 = Kg + ((size_t)kt << 13);   // kt*64*64*2
        const char* V0 = Vg + ((size_t)kt << 13);
        uint32_t ks = sb + AT_KV0 + stg * AT_STG;
        for (int i = tid; i < 512; i += 256) {
            int r = i >> 3, c = (i & 7) * 16;
            cp_async16(ks + r * AT_ROW + c, K0 + (size_t)r * 128 + c);
            cp_async16(ks + 9216 + r * AT_ROW + c, V0 + (size_t)r * 128 + c);
        }
        cp_commit();
    };

    loadKV(0, 0);
    asm volatile("cp.async.wait_group 0;" ::: "memory");
    __syncthreads();

    // Q fragments (persistent)
    int r0 = wid * 16;
    uint32_t qf[4][4];
    {
        uint32_t base = sb + AT_QOFF + (r0 + (lane & 15)) * AT_ROW + (lane >> 4) * 16;
        #pragma unroll
        for (int kb = 0; kb < 4; kb++)
            ldmx4(qf[kb][0], qf[kb][1], qf[kb][2], qf[kb][3], base + kb * 32);
    }

    float o[8][4];
    #pragma unroll
    for (int nd = 0; nd < 8; nd++)
        #pragma unroll
        for (int j = 0; j < 4; j++) o[nd][j] = 0.f;
    float m0 = -1e30f, m1 = -1e30f, l0 = 0.f, l1 = 0.f;

    const int KT = NN / 64;   // 32 tiles
    for (int kt = 0; kt < KT; kt++) {
        int stg = kt & 1;
        if (kt + 1 < KT) {
            loadKV(kt + 1, stg ^ 1);
            asm volatile("cp.async.wait_group 1;" ::: "memory");
        } else {
            asm volatile("cp.async.wait_group 0;" ::: "memory");
        }
        __syncthreads();

        uint32_t Kst = sb + AT_KV0 + stg * AT_STG;
        uint32_t Vst = Kst + 9216;

        // ---- scores S = Q K'^T : 16 x 64 per warp ----
        float sc[8][4];
        #pragma unroll
        for (int nb = 0; nb < 8; nb++)
            #pragma unroll
            for (int j = 0; j < 4; j++) sc[nb][j] = 0.f;

        int j2 = lane >> 3;             // matrix index 0..3
        int rin = lane & 7;
        #pragma unroll
        for (int p = 0; p < 4; p++) {   // key 16-blocks
            #pragma unroll
            for (int kb = 0; kb < 4; kb++) {   // d 16-blocks
                uint32_t addr = Kst + (p * 16 + (j2 >> 1) * 8 + rin) * AT_ROW
                                    + kb * 32 + (j2 & 1) * 16;
                uint32_t b0, b1, b2, b3;
                ldmx4(b0, b1, b2, b3, addr);
                mma16816(sc[2 * p + 0], qf[kb], b0, b1);
                mma16816(sc[2 * p + 1], qf[kb], b2, b3);
            }
        }

        // ---- online softmax ----
        float mx0 = -1e30f, mx1 = -1e30f;
        #pragma unroll
        for (int nb = 0; nb < 8; nb++) {
            mx0 = fmaxf(mx0, fmaxf(sc[nb][0], sc[nb][1]));
            mx1 = fmaxf(mx1, fmaxf(sc[nb][2], sc[nb][3]));
        }
        mx0 = fmaxf(mx0, __shfl_xor_sync(0xffffffffu, mx0, 1));
        mx0 = fmaxf(mx0, __shfl_xor_sync(0xffffffffu, mx0, 2));
        mx1 = fmaxf(mx1, __shfl_xor_sync(0xffffffffu, mx1, 1));
        mx1 = fmaxf(mx1, __shfl_xor_sync(0xffffffffu, mx1, 2));

        float mn0 = fmaxf(m0, mx0), mn1 = fmaxf(m1, mx1);
        float corr0 = __expf(m0 - mn0), corr1 = __expf(m1 - mn1);
        m0 = mn0; m1 = mn1;

        uint32_t pa[8], pb[8];
        float sum0 = 0.f, sum1 = 0.f;
        #pragma unroll
        for (int nb = 0; nb < 8; nb++) {
            float p0 = __expf(sc[nb][0] - mn0);
            float p1 = __expf(sc[nb][1] - mn0);
            float p2 = __expf(sc[nb][2] - mn1);
            float p3 = __expf(sc[nb][3] - mn1);
            sum0 += p0 + p1; sum1 += p2 + p3;
            pa[nb] = pack_bf16(p0, p1);
            pb[nb] = pack_bf16(p2, p3);
        }
        sum0 += __shfl_xor_sync(0xffffffffu, sum0, 1);
        sum0 += __shfl_xor_sync(0xffffffffu, sum0, 2);
        sum1 += __shfl_xor_sync(0xffffffffu, sum1, 1);
        sum1 += __shfl_xor_sync(0xffffffffu, sum1, 2);
        l0 = l0 * corr0 + sum0;
        l1 = l1 * corr1 + sum1;

        #pragma unroll
        for (int nd = 0; nd < 8; nd++) {
            o[nd][0] *= corr0; o[nd][1] *= corr0;
            o[nd][2] *= corr1; o[nd][3] *= corr1;
        }

        // ---- O += P V ----
        #pragma unroll
        for (int kb = 0; kb < 4; kb++) {       // key 16-blocks
            uint32_t a[4] = { pa[2 * kb], pb[2 * kb], pa[2 * kb + 1], pb[2 * kb + 1] };
            #pragma unroll
            for (int v = 0; v < 4; v++) {      // d 16-blocks
                uint32_t addr = Vst + (kb * 16 + (j2 & 1) * 8 + rin) * AT_ROW
                                    + v * 32 + (j2 >> 1) * 16;
                uint32_t b0, b1, b2, b3;
                ldmx4t(b0, b1, b2, b3, addr);
                mma16816(o[2 * v + 0], a, b0, b1);
                mma16816(o[2 * v + 1], a, b2, b3);
            }
        }
        __syncthreads();
    }

    // ---- epilogue: multiply by gate, write bf16 ----
    float inv0 = 1.0f / l0, inv1 = 1.0f / l1;
    int rowa = tq0 + r0 + (lane >> 2);
    size_t toka = (size_t)b * NN + rowa;
    size_t tokb = toka + 8;
    int cb = h * DD + (lane & 3) * 2;
    #pragma unroll
    for (int nd = 0; nd < 8; nd++) {
        int d = cb + nd * 8;
        float2 ga = *(const float2*)(gate + toka * CC + d);
        float2 gb = *(const float2*)(gate + tokb * CC + d);
        *(uint32_t*)(outb + toka * CC + d) = pack_bf16(o[nd][0] * inv0 * ga.x,
                                                       o[nd][1] * inv0 * ga.y);
        *(uint32_t*)(outb + tokb * CC + d) = pack_bf16(o[nd][2] * inv1 * gb.x,
                                                       o[nd][3] * inv1 * gb.y);
    }
}

// ---------------------------------------------------------------------------
extern "C" void kernel_launch(void* const* d_in, const int* in_sizes, int n_in,
                              void* d_out, int out_size) {
    const float* x      = (const float*)d_in[0];
    const float* e      = (const float*)d_in[1];
    const float* w_qkv  = (const float*)d_in[2];
    const float* w_s    = (const float*)d_in[3];
    const float* w_gate = (const float*)d_in[4];
    const float* w_proj = (const float*)d_in[5];
    const float* b_proj = (const float*)d_in[6];
    const float* ln1_w  = (const float*)d_in[7];
    const float* ln1_b  = (const float*)d_in[8];
    const float* ln2_w  = (const float*)d_in[9];
    const float* ln2_b  = (const float*)d_in[10];
    const float* ln3_w  = (const float*)d_in[11];
    const float* ln3_b  = (const float*)d_in[12];
    const float* w_fc1  = (const float*)d_in[13];
    const float* b_fc1  = (const float*)d_in[14];
    const float* w_fc2  = (const float*)d_in[15];
    const float* b_fc2  = (const float*)d_in[16];
    float* out = (float*)d_out;

    void* scr_v = nullptr;
    cudaGetSymbolAddress(&scr_v, g_scratch);
    float* scr = (float*)scr_v;
    float*         g_qkv  = scr + OFF_QKV;
    float*         g_s    = scr + OFF_S;
    float*         g_gate = scr + OFF_GATE;
    float*         g_x1   = scr + OFF_X1;
    __nv_bfloat16* g_xnb  = (__nv_bfloat16*)(scr + OFF_XNB);
    __nv_bfloat16* g_enb  = (__nv_bfloat16*)(scr + OFF_ENB);
    __nv_bfloat16* g_xn3b = (__nv_bfloat16*)(scr + OFF_XN3B);
    __nv_bfloat16* g_agb  = (__nv_bfloat16*)(scr + OFF_AGB);
    __nv_bfloat16* g_hb   = (__nv_bfloat16*)(scr + OFF_HB);
    __nv_bfloat16* wqkvT  = (__nv_bfloat16*)(scr + OFF_WQKVT);
    __nv_bfloat16* wsT    = (__nv_bfloat16*)(scr + OFF_WST);
    __nv_bfloat16* wgT    = (__nv_bfloat16*)(scr + OFF_WGT);
    __nv_bfloat16* wpT    = (__nv_bfloat16*)(scr + OFF_WPT);
    __nv_bfloat16* wf1T   = (__nv_bfloat16*)(scr + OFF_WF1T);
    __nv_bfloat16* wf2T   = (__nv_bfloat16*)(scr + OFF_WF2T);
    __nv_bfloat16* g_qh   = (__nv_bfloat16*)(scr + OFF_QH);
    __nv_bfloat16* g_kh   = (__nv_bfloat16*)(scr + OFF_KH);
    __nv_bfloat16* g_vh   = (__nv_bfloat16*)(scr + OFF_VH);

    cudaFuncSetAttribute(attn_kernel, cudaFuncAttributeMaxDynamicSharedMemorySize, AT_SMEM);

    dim3 tb(32, 8);
    wt_kernel<<<dim3(3 * CC / 32, CC / 32), tb>>>(w_qkv, wqkvT, CC, 3 * CC);
    wt_kernel<<<dim3(CC / 32, CC / 32), tb>>>(w_s,    wsT,  CC, CC);
    wt_kernel<<<dim3(CC / 32, CC / 32), tb>>>(w_gate, wgT,  CC, CC);
    wt_kernel<<<dim3(CC / 32, CC / 32), tb>>>(w_proj, wpT,  CC, CC);
    wt_kernel<<<dim3(FF / 32, CC / 32), tb>>>(w_fc1,  wf1T, CC, FF);
    wt_kernel<<<dim3(CC / 32, FF / 32), tb>>>(w_fc2,  wf2T, FF, CC);

    ln_kernel<<<TT, 128>>>(x, ln1_w, ln1_b, g_xnb);
    ln_kernel<<<TT, 128>>>(e, ln2_w, ln2_b, g_enb);

    mm_kernel<0, false><<<dim3(3 * CC / 128, TT / 128), 256>>>(
        g_xnb, wqkvT, nullptr, nullptr, g_qkv, TT, 3 * CC, CC);
    mm_kernel<0, false><<<dim3(CC / 128, TT / 128), 256>>>(
        g_enb, wsT, nullptr, nullptr, g_s, TT, CC, CC);
    mm_kernel<0, false><<<dim3(CC / 128, TT / 128), 256>>>(
        g_xnb, wgT, nullptr, nullptr, g_gate, TT, CC, CC);

    qkvprep_kernel<<<TT, 256>>>(g_qkv, g_s, g_qh, g_kh, g_vh);

    attn_kernel<<<dim3(NN / 128, HH, BB), 256, AT_SMEM>>>(g_qh, g_kh, g_vh, g_gate, g_agb);

    mm_kernel<0, false><<<dim3(CC / 128, TT / 128), 256>>>(
        g_agb, wpT, b_proj, x, g_x1, TT, CC, CC);

    ln_kernel<<<TT, 128>>>(g_x1, ln3_w, ln3_b, g_xn3b);

    mm_kernel<1, true><<<dim3(FF / 128, TT / 128), 256>>>(
        g_xn3b, wf1T, b_fc1, nullptr, g_hb, TT, FF, CC);

    mm_kernel<0, false><<<dim3(CC / 128, TT / 128), 256>>>(
        g_hb, wf2T, b_fc2, g_x1, out, TT, CC, FF);
}

// round 9
// speedup vs baseline: 6.1876x; 1.4065x over previous
#include <cuda_runtime.h>
#include <cuda_bf16.h>
#include <math.h>
#include <cstdint>

// Problem constants
#define BB 4
#define NN 2048
#define CC 512
#define HH 8
#define DD 64
#define TT (BB*NN)          // 8192 tokens
#define FF 2048             // d_ff

// ---------------------------------------------------------------------------
// Scratch layout (float units)
#define OFF_S     0ull          // fp32 [TT, C]
#define OFF_GATE  4194304ull    // fp32 [TT, C]
#define OFF_X1    8388608ull    // fp32 [TT, C]
#define OFF_XNB   12582912ull   // bf16 [TT, C]
#define OFF_ENB   14680064ull   // bf16 [TT, C]
#define OFF_XN3B  16777216ull   // bf16 [TT, C]
#define OFF_AGB   18874368ull   // bf16 [TT, C]
#define OFF_HB    20971520ull   // bf16 [TT, FF]
#define OFF_WQKVG 29360128ull   // bf16 [2048, 512]  (rows: wqkvT 0..1535, wgT 1536..2047)
#define OFF_WST   29884416ull   // bf16 [C, C]
#define OFF_WPT   30015488ull   // bf16 [C, C]
#define OFF_WF1T  30146560ull   // bf16 [FF, C]
#define OFF_WF2T  30670848ull   // bf16 [C, FF]
#define OFF_QH    31195136ull   // bf16 [B*H, N, 64]
#define OFF_KH    33292288ull   // bf16 [B*H, N, 64]
#define OFF_VH    35389440ull   // bf16 [B*H, N, 64]
#define SCRATCH_FLOATS 37486592ull

__device__ float g_scratch[SCRATCH_FLOATS];

// ---------------------------------------------------------------------------
__device__ __forceinline__ uint32_t smem_u32(const void* p) {
    uint32_t a;
    asm("{ .reg .u64 t; cvta.to.shared.u64 t, %1; cvt.u32.u64 %0, t; }" : "=r"(a) : "l"(p));
    return a;
}
__device__ __forceinline__ void cp_async16(uint32_t saddr, const void* gaddr) {
    asm volatile("cp.async.cg.shared.global [%0], [%1], 16;" :: "r"(saddr), "l"(gaddr) : "memory");
}
__device__ __forceinline__ void cp_commit() {
    asm volatile("cp.async.commit_group;" ::: "memory");
}
__device__ __forceinline__ void ldmx4(uint32_t& r0, uint32_t& r1, uint32_t& r2, uint32_t& r3,
                                      uint32_t addr) {
    asm volatile("ldmatrix.sync.aligned.m8n8.x4.shared.b16 {%0,%1,%2,%3}, [%4];"
                 : "=r"(r0), "=r"(r1), "=r"(r2), "=r"(r3) : "r"(addr));
}
__device__ __forceinline__ void ldmx4t(uint32_t& r0, uint32_t& r1, uint32_t& r2, uint32_t& r3,
                                       uint32_t addr) {
    asm volatile("ldmatrix.sync.aligned.m8n8.x4.trans.shared.b16 {%0,%1,%2,%3}, [%4];"
                 : "=r"(r0), "=r"(r1), "=r"(r2), "=r"(r3) : "r"(addr));
}
__device__ __forceinline__ void mma16816(float* c, const uint32_t* a, uint32_t b0, uint32_t b1) {
    asm volatile(
        "mma.sync.aligned.m16n8k16.row.col.f32.bf16.bf16.f32 "
        "{%0,%1,%2,%3}, {%4,%5,%6,%7}, {%8,%9}, {%0,%1,%2,%3};"
        : "+f"(c[0]), "+f"(c[1]), "+f"(c[2]), "+f"(c[3])
        : "r"(a[0]), "r"(a[1]), "r"(a[2]), "r"(a[3]), "r"(b0), "r"(b1));
}
__device__ __forceinline__ uint32_t pack_bf16(float a, float b) {
    __nv_bfloat162 p = __floats2bfloat162_rn(a, b);
    return *(uint32_t*)&p;
}

// ---------------------------------------------------------------------------
// LayerNorm -> bf16 output
__global__ void ln_kernel(const float* __restrict__ x,
                          const float* __restrict__ w,
                          const float* __restrict__ b,
                          __nv_bfloat16* __restrict__ y) {
    int row = blockIdx.x;
    int tid = threadIdx.x;
    const float4* xr = (const float4*)(x + (size_t)row * CC);
    float4 v = xr[tid];
    float s  = v.x + v.y + v.z + v.w;
    float ss = v.x*v.x + v.y*v.y + v.z*v.z + v.w*v.w;
    #pragma unroll
    for (int off = 16; off; off >>= 1) {
        s  += __shfl_xor_sync(0xffffffffu, s,  off);
        ss += __shfl_xor_sync(0xffffffffu, ss, off);
    }
    __shared__ float sm[4], sm2[4];
    int warp = tid >> 5, lane = tid & 31;
    if (lane == 0) { sm[warp] = s; sm2[warp] = ss; }
    __syncthreads();
    float tot  = sm[0] + sm[1] + sm[2] + sm[3];
    float tot2 = sm2[0] + sm2[1] + sm2[2] + sm2[3];
    float mu   = tot * (1.0f / CC);
    float var  = tot2 * (1.0f / CC) - mu * mu;
    float rstd = rsqrtf(var + 1e-5f);
    float4 wv = ((const float4*)w)[tid];
    float4 bv = ((const float4*)b)[tid];
    uint2 o;
    o.x = pack_bf16((v.x - mu) * rstd * wv.x + bv.x, (v.y - mu) * rstd * wv.y + bv.y);
    o.y = pack_bf16((v.z - mu) * rstd * wv.z + bv.z, (v.w - mu) * rstd * wv.w + bv.w);
    ((uint2*)(y + (size_t)row * CC))[tid] = o;
}

// ---------------------------------------------------------------------------
// Weight transpose + fp32->bf16: W[K,N] -> WT[N,K]
__global__ void wt_kernel(const float* __restrict__ W, __nv_bfloat16* __restrict__ WT,
                          int K, int N) {
    __shared__ float t[32][33];
    int k0 = blockIdx.y * 32, n0 = blockIdx.x * 32;
    int tx = threadIdx.x, ty = threadIdx.y;   // 32 x 8
    #pragma unroll
    for (int i = 0; i < 32; i += 8)
        t[ty + i][tx] = W[(size_t)(k0 + ty + i) * N + n0 + tx];
    __syncthreads();
    #pragma unroll
    for (int i = 0; i < 32; i += 8)
        WT[(size_t)(n0 + ty + i) * K + k0 + tx] = __float2bfloat16(t[tx][ty + i]);
}

// ---------------------------------------------------------------------------
// mm2: HMMA bf16 GEMM, 256x128 CTA tile, 64x64 warp tile, BK=32, 3-stage cp.async.
// MODE 0: fp32 out = A@Bt^T (+bias) (+res)
// MODE 1: bf16 out = gelu(A@Bt^T + bias)
// MODE 2: qkvg epilogue (N=2048): seg0 q*0.125->qh, seg1 k+s->kh, seg2 v->vh,
//         seg3 gate fp32. Per-head layouts.
#define M2_ROW  80
#define M2_B    20480           // A: 256 rows; B at row 256
#define M2_STG  30720           // 384 * 80
#define M2_SMEM (3 * M2_STG)    // 92160

template<int MODE>
__global__ void __launch_bounds__(256) mm2_kernel(
    const __nv_bfloat16* __restrict__ A,   // [M,K]
    const __nv_bfloat16* __restrict__ Bt,  // [N,K]
    const float* __restrict__ bias,
    const float* __restrict__ res,
    const float* __restrict__ sextra,      // MODE 2: s [TT, 512]
    float* __restrict__ outf,              // MODE 0 / MODE 2 gate
    __nv_bfloat16* __restrict__ outb0,     // MODE 1 out / MODE 2 qh
    __nv_bfloat16* __restrict__ outb1,     // MODE 2 kh
    __nv_bfloat16* __restrict__ outb2,     // MODE 2 vh
    int M, int N, int K)
{
    extern __shared__ __align__(16) char smem[];
    uint32_t sb = smem_u32(smem);

    int tid = threadIdx.x, wid = tid >> 5, lane = tid & 31;
    int m0 = blockIdx.y * 256, n0 = blockIdx.x * 128;
    int wm = wid & 3, wn = wid >> 2;        // 4 x 2 warps, 64x64 each

    const char* Abase = (const char*)A;
    const char* Bbase = (const char*)Bt;
    size_t rstride = (size_t)K * 2;
    int KC = K >> 5;

    auto load_tile = [&](int kc, int stg) {
        uint32_t base = sb + stg * M2_STG;
        size_t koff = (size_t)kc * 64;
        #pragma unroll
        for (int i = 0; i < 6; i++) {
            int idx = i * 256 + tid;         // 0..1535
            int row = idx >> 2;              // 0..383
            int c = (idx & 3) * 16;
            const char* g = (row < 256)
                ? Abase + (size_t)(m0 + row) * rstride + koff + c
                : Bbase + (size_t)(n0 + row - 256) * rstride + koff + c;
            cp_async16(base + row * M2_ROW + c, g);
        }
        cp_commit();
    };

    float acc[4][8][4];
    #pragma unroll
    for (int mi = 0; mi < 4; mi++)
        #pragma unroll
        for (int nb = 0; nb < 8; nb++)
            #pragma unroll
            for (int j = 0; j < 4; j++) acc[mi][nb][j] = 0.f;

    load_tile(0, 0);
    load_tile(1, 1);

    uint32_t lrow16 = (lane & 15);
    uint32_t lkhalf = (lane >> 4) * 16;

    for (int kc = 0; kc < KC; kc++) {
        if (kc < KC - 1) asm volatile("cp.async.wait_group 1;" ::: "memory");
        else             asm volatile("cp.async.wait_group 0;" ::: "memory");
        __syncthreads();

        if (kc + 2 < KC) load_tile(kc + 2, (kc + 2) % 3);

        int stg = kc % 3;
        uint32_t sA = sb + stg * M2_STG + (wm * 64 + lrow16) * M2_ROW + lkhalf;
        uint32_t sB = sb + stg * M2_STG + M2_B + (wn * 64 + lrow16) * M2_ROW + lkhalf;

        #pragma unroll
        for (int ks = 0; ks < 2; ks++) {
            uint32_t koff = ks * 32;
            uint32_t a[4][4];
            #pragma unroll
            for (int mi = 0; mi < 4; mi++)
                ldmx4(a[mi][0], a[mi][1], a[mi][2], a[mi][3],
                      sA + mi * 16 * M2_ROW + koff);
            uint32_t b[4][4];
            #pragma unroll
            for (int nb = 0; nb < 4; nb++)
                ldmx4(b[nb][0], b[nb][1], b[nb][2], b[nb][3],
                      sB + nb * 16 * M2_ROW + koff);
            #pragma unroll
            for (int mi = 0; mi < 4; mi++)
                #pragma unroll
                for (int nb = 0; nb < 4; nb++) {
                    mma16816(acc[mi][nb * 2 + 0], a[mi], b[nb][0], b[nb][2]);
                    mma16816(acc[mi][nb * 2 + 1], a[mi], b[nb][1], b[nb][3]);
                }
        }
    }

    // ---- epilogue ----
    int mbase = m0 + wm * 64 + (lane >> 2);
    int nbase = n0 + wn * 64 + (lane & 3) * 2;
    int seg = nbase >> 9;          // uniform per warp (MODE 2)

    #pragma unroll
    for (int mi = 0; mi < 4; mi++) {
        #pragma unroll
        for (int nb = 0; nb < 8; nb++) {
            int n = nbase + nb * 8;
            #pragma unroll
            for (int half = 0; half < 2; half++) {
                int m = mbase + mi * 16 + half * 8;
                float v0 = acc[mi][nb][half * 2 + 0];
                float v1 = acc[mi][nb][half * 2 + 1];
                if (MODE == 0) {
                    if (bias) { v0 += bias[n]; v1 += bias[n + 1]; }
                    if (res) {
                        const float* rp = res + (size_t)m * N + n;
                        v0 += rp[0]; v1 += rp[1];
                    }
                    *(float2*)(outf + (size_t)m * N + n) = make_float2(v0, v1);
                } else if (MODE == 1) {
                    v0 += bias[n]; v1 += bias[n + 1];
                    v0 = 0.5f * v0 * (1.0f + erff(v0 * 0.70710678118654752f));
                    v1 = 0.5f * v1 * (1.0f + erff(v1 * 0.70710678118654752f));
                    *(uint32_t*)(outb0 + (size_t)m * N + n) = pack_bf16(v0, v1);
                } else {
                    int c = n & 511;
                    int bidx = m >> 11, nloc = m & (NN - 1);
                    if (seg == 3) {
                        *(float2*)(outf + (size_t)m * CC + c) = make_float2(v0, v1);
                    } else {
                        int h = c >> 6, d = c & 63;
                        size_t ph = (((size_t)(bidx * HH + h) * NN + nloc) << 6) + d;
                        if (seg == 0) {
                            *(uint32_t*)(outb0 + ph) = pack_bf16(v0 * 0.125f, v1 * 0.125f);
                        } else if (seg == 1) {
                            float2 sv = *(const float2*)(sextra + (size_t)m * CC + c);
                            *(uint32_t*)(outb1 + ph) = pack_bf16(v0 + sv.x, v1 + sv.y);
                        } else {
                            *(uint32_t*)(outb2 + ph) = pack_bf16(v0, v1);
                        }
                    }
                }
            }
        }
    }
}

// ---------------------------------------------------------------------------
// bf16 HMMA flash attention, fused gate-multiply epilogue.
#define AT_QOFF 0
#define AT_ROW  144
#define AT_KV0  18432
#define AT_STG  18432
#define AT_SMEM (18432 + 2 * 18432)

__global__ void __launch_bounds__(256) attn_kernel(
    const __nv_bfloat16* __restrict__ qh,
    const __nv_bfloat16* __restrict__ kh,
    const __nv_bfloat16* __restrict__ vh,
    const float* __restrict__ gate,
    __nv_bfloat16* __restrict__ outb)
{
    extern __shared__ char smem[];
    uint32_t sb = smem_u32(smem);
    int tid = threadIdx.x, wid = tid >> 5, lane = tid & 31;
    int qt = blockIdx.x, h = blockIdx.y, b = blockIdx.z;
    int bh = b * HH + h;
    int tq0 = qt * 128;

    const char* Qg = (const char*)(qh + (((size_t)bh * NN + tq0) << 6));
    const char* Kg = (const char*)(kh + ((size_t)bh * NN << 6));
    const char* Vg = (const char*)(vh + ((size_t)bh * NN << 6));

    for (int i = tid; i < 1024; i += 256) {
        int r = i >> 3, c = (i & 7) * 16;
        cp_async16(sb + AT_QOFF + r * AT_ROW + c, Qg + (size_t)r * 128 + c);
    }
    cp_commit();

    auto loadKV = [&](int kt, int stg) {
        const char* K0 = Kg + ((size_t)kt << 13);
        const char* V0 = Vg + ((size_t)kt << 13);
        uint32_t ks = sb + AT_KV0 + stg * AT_STG;
        for (int i = tid; i < 512; i += 256) {
            int r = i >> 3, c = (i & 7) * 16;
            cp_async16(ks + r * AT_ROW + c, K0 + (size_t)r * 128 + c);
            cp_async16(ks + 9216 + r * AT_ROW + c, V0 + (size_t)r * 128 + c);
        }
        cp_commit();
    };

    loadKV(0, 0);
    asm volatile("cp.async.wait_group 0;" ::: "memory");
    __syncthreads();

    int r0 = wid * 16;
    uint32_t qf[4][4];
    {
        uint32_t base = sb + AT_QOFF + (r0 + (lane & 15)) * AT_ROW + (lane >> 4) * 16;
        #pragma unroll
        for (int kb = 0; kb < 4; kb++)
            ldmx4(qf[kb][0], qf[kb][1], qf[kb][2], qf[kb][3], base + kb * 32);
    }

    float o[8][4];
    #pragma unroll
    for (int nd = 0; nd < 8; nd++)
        #pragma unroll
        for (int j = 0; j < 4; j++) o[nd][j] = 0.f;
    float m0 = -1e30f, m1 = -1e30f, l0 = 0.f, l1 = 0.f;

    const int KT = NN / 64;
    for (int kt = 0; kt < KT; kt++) {
        int stg = kt & 1;
        if (kt + 1 < KT) {
            loadKV(kt + 1, stg ^ 1);
            asm volatile("cp.async.wait_group 1;" ::: "memory");
        } else {
            asm volatile("cp.async.wait_group 0;" ::: "memory");
        }
        __syncthreads();

        uint32_t Kst = sb + AT_KV0 + stg * AT_STG;
        uint32_t Vst = Kst + 9216;

        float sc[8][4];
        #pragma unroll
        for (int nb = 0; nb < 8; nb++)
            #pragma unroll
            for (int j = 0; j < 4; j++) sc[nb][j] = 0.f;

        int j2 = lane >> 3;
        int rin = lane & 7;
        #pragma unroll
        for (int p = 0; p < 4; p++) {
            #pragma unroll
            for (int kb = 0; kb < 4; kb++) {
                uint32_t addr = Kst + (p * 16 + (j2 >> 1) * 8 + rin) * AT_ROW
                                    + kb * 32 + (j2 & 1) * 16;
                uint32_t b0, b1, b2, b3;
                ldmx4(b0, b1, b2, b3, addr);
                mma16816(sc[2 * p + 0], qf[kb], b0, b1);
                mma16816(sc[2 * p + 1], qf[kb], b2, b3);
            }
        }

        float mx0 = -1e30f, mx1 = -1e30f;
        #pragma unroll
        for (int nb = 0; nb < 8; nb++) {
            mx0 = fmaxf(mx0, fmaxf(sc[nb][0], sc[nb][1]));
            mx1 = fmaxf(mx1, fmaxf(sc[nb][2], sc[nb][3]));
        }
        mx0 = fmaxf(mx0, __shfl_xor_sync(0xffffffffu, mx0, 1));
        mx0 = fmaxf(mx0, __shfl_xor_sync(0xffffffffu, mx0, 2));
        mx1 = fmaxf(mx1, __shfl_xor_sync(0xffffffffu, mx1, 1));
        mx1 = fmaxf(mx1, __shfl_xor_sync(0xffffffffu, mx1, 2));

        float mn0 = fmaxf(m0, mx0), mn1 = fmaxf(m1, mx1);
        float corr0 = __expf(m0 - mn0), corr1 = __expf(m1 - mn1);
        m0 = mn0; m1 = mn1;

        uint32_t pa[8], pb[8];
        float sum0 = 0.f, sum1 = 0.f;
        #pragma unroll
        for (int nb = 0; nb < 8; nb++) {
            float p0 = __expf(sc[nb][0] - mn0);
            float p1 = __expf(sc[nb][1] - mn0);
            float p2 = __expf(sc[nb][2] - mn1);
            float p3 = __expf(sc[nb][3] - mn1);
            sum0 += p0 + p1; sum1 += p2 + p3;
            pa[nb] = pack_bf16(p0, p1);
            pb[nb] = pack_bf16(p2, p3);
        }
        sum0 += __shfl_xor_sync(0xffffffffu, sum0, 1);
        sum0 += __shfl_xor_sync(0xffffffffu, sum0, 2);
        sum1 += __shfl_xor_sync(0xffffffffu, sum1, 1);
        sum1 += __shfl_xor_sync(0xffffffffu, sum1, 2);
        l0 = l0 * corr0 + sum0;
        l1 = l1 * corr1 + sum1;

        #pragma unroll
        for (int nd = 0; nd < 8; nd++) {
            o[nd][0] *= corr0; o[nd][1] *= corr0;
            o[nd][2] *= corr1; o[nd][3] *= corr1;
        }

        #pragma unroll
        for (int kb = 0; kb < 4; kb++) {
            uint32_t a[4] = { pa[2 * kb], pb[2 * kb], pa[2 * kb + 1], pb[2 * kb + 1] };
            #pragma unroll
            for (int v = 0; v < 4; v++) {
                uint32_t addr = Vst + (kb * 16 + (j2 & 1) * 8 + rin) * AT_ROW
                                    + v * 32 + (j2 >> 1) * 16;
                uint32_t b0, b1, b2, b3;
                ldmx4t(b0, b1, b2, b3, addr);
                mma16816(o[2 * v + 0], a, b0, b1);
                mma16816(o[2 * v + 1], a, b2, b3);
            }
        }
        __syncthreads();
    }

    float inv0 = 1.0f / l0, inv1 = 1.0f / l1;
    int rowa = tq0 + r0 + (lane >> 2);
    size_t toka = (size_t)b * NN + rowa;
    size_t tokb = toka + 8;
    int cb = h * DD + (lane & 3) * 2;
    #pragma unroll
    for (int nd = 0; nd < 8; nd++) {
        int d = cb + nd * 8;
        float2 ga = *(const float2*)(gate + toka * CC + d);
        float2 gb = *(const float2*)(gate + tokb * CC + d);
        *(uint32_t*)(outb + toka * CC + d) = pack_bf16(o[nd][0] * inv0 * ga.x,
                                                       o[nd][1] * inv0 * ga.y);
        *(uint32_t*)(outb + tokb * CC + d) = pack_bf16(o[nd][2] * inv1 * gb.x,
                                                       o[nd][3] * inv1 * gb.y);
    }
}

// ---------------------------------------------------------------------------
extern "C" void kernel_launch(void* const* d_in, const int* in_sizes, int n_in,
                              void* d_out, int out_size) {
    const float* x      = (const float*)d_in[0];
    const float* e      = (const float*)d_in[1];
    const float* w_qkv  = (const float*)d_in[2];
    const float* w_s    = (const float*)d_in[3];
    const float* w_gate = (const float*)d_in[4];
    const float* w_proj = (const float*)d_in[5];
    const float* b_proj = (const float*)d_in[6];
    const float* ln1_w  = (const float*)d_in[7];
    const float* ln1_b  = (const float*)d_in[8];
    const float* ln2_w  = (const float*)d_in[9];
    const float* ln2_b  = (const float*)d_in[10];
    const float* ln3_w  = (const float*)d_in[11];
    const float* ln3_b  = (const float*)d_in[12];
    const float* w_fc1  = (const float*)d_in[13];
    const float* b_fc1  = (const float*)d_in[14];
    const float* w_fc2  = (const float*)d_in[15];
    const float* b_fc2  = (const float*)d_in[16];
    float* out = (float*)d_out;

    void* scr_v = nullptr;
    cudaGetSymbolAddress(&scr_v, g_scratch);
    float* scr = (float*)scr_v;
    float*         g_s    = scr + OFF_S;
    float*         g_gate = scr + OFF_GATE;
    float*         g_x1   = scr + OFF_X1;
    __nv_bfloat16* g_xnb  = (__nv_bfloat16*)(scr + OFF_XNB);
    __nv_bfloat16* g_enb  = (__nv_bfloat16*)(scr + OFF_ENB);
    __nv_bfloat16* g_xn3b = (__nv_bfloat16*)(scr + OFF_XN3B);
    __nv_bfloat16* g_agb  = (__nv_bfloat16*)(scr + OFF_AGB);
    __nv_bfloat16* g_hb   = (__nv_bfloat16*)(scr + OFF_HB);
    __nv_bfloat16* wqkvg  = (__nv_bfloat16*)(scr + OFF_WQKVG);
    __nv_bfloat16* wsT    = (__nv_bfloat16*)(scr + OFF_WST);
    __nv_bfloat16* wpT    = (__nv_bfloat16*)(scr + OFF_WPT);
    __nv_bfloat16* wf1T   = (__nv_bfloat16*)(scr + OFF_WF1T);
    __nv_bfloat16* wf2T   = (__nv_bfloat16*)(scr + OFF_WF2T);
    __nv_bfloat16* g_qh   = (__nv_bfloat16*)(scr + OFF_QH);
    __nv_bfloat16* g_kh   = (__nv_bfloat16*)(scr + OFF_KH);
    __nv_bfloat16* g_vh   = (__nv_bfloat16*)(scr + OFF_VH);

    cudaFuncSetAttribute(attn_kernel, cudaFuncAttributeMaxDynamicSharedMemorySize, AT_SMEM);
    cudaFuncSetAttribute(mm2_kernel<0>, cudaFuncAttributeMaxDynamicSharedMemorySize, M2_SMEM);
    cudaFuncSetAttribute(mm2_kernel<1>, cudaFuncAttributeMaxDynamicSharedMemorySize, M2_SMEM);
    cudaFuncSetAttribute(mm2_kernel<2>, cudaFuncAttributeMaxDynamicSharedMemorySize, M2_SMEM);

    dim3 tb(32, 8);
    // weights: combined [wqkvT ; wgT] then the rest
    wt_kernel<<<dim3(3 * CC / 32, CC / 32), tb>>>(w_qkv, wqkvg, CC, 3 * CC);
    wt_kernel<<<dim3(CC / 32, CC / 32), tb>>>(w_gate, wqkvg + (size_t)1536 * CC, CC, CC);
    wt_kernel<<<dim3(CC / 32, CC / 32), tb>>>(w_s,    wsT,  CC, CC);
    wt_kernel<<<dim3(CC / 32, CC / 32), tb>>>(w_proj, wpT,  CC, CC);
    wt_kernel<<<dim3(FF / 32, CC / 32), tb>>>(w_fc1,  wf1T, CC, FF);
    wt_kernel<<<dim3(CC / 32, FF / 32), tb>>>(w_fc2,  wf2T, FF, CC);

    ln_kernel<<<TT, 128>>>(x, ln1_w, ln1_b, g_xnb);
    ln_kernel<<<TT, 128>>>(e, ln2_w, ln2_b, g_enb);

    // s = en @ w_s  (fp32, needed by qkvg epilogue)
    mm2_kernel<0><<<dim3(CC / 128, TT / 256), 256, M2_SMEM>>>(
        g_enb, wsT, nullptr, nullptr, nullptr, g_s, nullptr, nullptr, nullptr,
        TT, CC, CC);

    // fused qkv+gate GEMM with per-head scatter epilogue
    mm2_kernel<2><<<dim3(2048 / 128, TT / 256), 256, M2_SMEM>>>(
        g_xnb, wqkvg, nullptr, nullptr, g_s, g_gate, g_qh, g_kh, g_vh,
        TT, 2048, CC);

    attn_kernel<<<dim3(NN / 128, HH, BB), 256, AT_SMEM>>>(g_qh, g_kh, g_vh, g_gate, g_agb);

    // x1 = x + ag @ w_proj + b_proj
    mm2_kernel<0><<<dim3(CC / 128, TT / 256), 256, M2_SMEM>>>(
        g_agb, wpT, b_proj, x, nullptr, g_x1, nullptr, nullptr, nullptr,
        TT, CC, CC);

    ln_kernel<<<TT, 128>>>(g_x1, ln3_w, ln3_b, g_xn3b);

    // h = gelu(xn3 @ w_fc1 + b_fc1) -> bf16
    mm2_kernel<1><<<dim3(FF / 128, TT / 256), 256, M2_SMEM>>>(
        g_xn3b, wf1T, b_fc1, nullptr, nullptr, nullptr, g_hb, nullptr, nullptr,
        TT, FF, CC);

    // out = x1 + h @ w_fc2 + b_fc2
    mm2_kernel<0><<<dim3(CC / 128, TT / 256), 256, M2_SMEM>>>(
        g_hb, wf2T, b_fc2, g_x1, nullptr, out, nullptr, nullptr, nullptr,
        TT, CC, FF);
}

// round 10
// speedup vs baseline: 6.3206x; 1.0215x over previous
#include <cuda_runtime.h>
#include <cuda_bf16.h>
#include <math.h>
#include <cstdint>

// Problem constants
#define BB 4
#define NN 2048
#define CC 512
#define HH 8
#define DD 64
#define TT (BB*NN)          // 8192 tokens
#define FF 2048             // d_ff

// ---------------------------------------------------------------------------
// Scratch layout (float units)
#define OFF_S     0ull          // fp32 [TT, C]
#define OFF_GATE  4194304ull    // fp32 [TT, C]
#define OFF_X1    8388608ull    // fp32 [TT, C]
#define OFF_XNB   12582912ull   // bf16 [TT, C]
#define OFF_ENB   14680064ull   // bf16 [TT, C]
#define OFF_XN3B  16777216ull   // bf16 [TT, C]
#define OFF_AGB   18874368ull   // bf16 [TT, C]
#define OFF_HB    20971520ull   // bf16 [TT, FF]
#define OFF_WQKVG 29360128ull   // bf16 [2048, 512]  (rows: wqkvT 0..1535, wgT 1536..2047)
#define OFF_WST   29884416ull   // bf16 [C, C]
#define OFF_WPT   30015488ull   // bf16 [C, C]
#define OFF_WF1T  30146560ull   // bf16 [FF, C]
#define OFF_WF2T  30670848ull   // bf16 [C, FF]
#define OFF_QH    31195136ull   // bf16 [B*H, N, 64]
#define OFF_KH    33292288ull   // bf16 [B*H, N, 64]
#define OFF_VH    35389440ull   // bf16 [B*H, N, 64]
#define SCRATCH_FLOATS 37486592ull

__device__ float g_scratch[SCRATCH_FLOATS];

// ---------------------------------------------------------------------------
__device__ __forceinline__ uint32_t smem_u32(const void* p) {
    uint32_t a;
    asm("{ .reg .u64 t; cvta.to.shared.u64 t, %1; cvt.u32.u64 %0, t; }" : "=r"(a) : "l"(p));
    return a;
}
__device__ __forceinline__ void cp_async16(uint32_t saddr, const void* gaddr) {
    asm volatile("cp.async.cg.shared.global [%0], [%1], 16;" :: "r"(saddr), "l"(gaddr) : "memory");
}
__device__ __forceinline__ void cp_commit() {
    asm volatile("cp.async.commit_group;" ::: "memory");
}
__device__ __forceinline__ void ldmx4(uint32_t& r0, uint32_t& r1, uint32_t& r2, uint32_t& r3,
                                      uint32_t addr) {
    asm volatile("ldmatrix.sync.aligned.m8n8.x4.shared.b16 {%0,%1,%2,%3}, [%4];"
                 : "=r"(r0), "=r"(r1), "=r"(r2), "=r"(r3) : "r"(addr));
}
__device__ __forceinline__ void ldmx4t(uint32_t& r0, uint32_t& r1, uint32_t& r2, uint32_t& r3,
                                       uint32_t addr) {
    asm volatile("ldmatrix.sync.aligned.m8n8.x4.trans.shared.b16 {%0,%1,%2,%3}, [%4];"
                 : "=r"(r0), "=r"(r1), "=r"(r2), "=r"(r3) : "r"(addr));
}
__device__ __forceinline__ void mma16816(float* c, const uint32_t* a, uint32_t b0, uint32_t b1) {
    asm volatile(
        "mma.sync.aligned.m16n8k16.row.col.f32.bf16.bf16.f32 "
        "{%0,%1,%2,%3}, {%4,%5,%6,%7}, {%8,%9}, {%0,%1,%2,%3};"
        : "+f"(c[0]), "+f"(c[1]), "+f"(c[2]), "+f"(c[3])
        : "r"(a[0]), "r"(a[1]), "r"(a[2]), "r"(a[3]), "r"(b0), "r"(b1));
}
__device__ __forceinline__ uint32_t pack_bf16(float a, float b) {
    __nv_bfloat162 p = __floats2bfloat162_rn(a, b);
    return *(uint32_t*)&p;
}

// ---------------------------------------------------------------------------
// Fused LayerNorm for LN1(x) and LN2(e): blockIdx.y selects.
__global__ void ln2x_kernel(const float* __restrict__ x, const float* __restrict__ e,
                            const float* __restrict__ w1, const float* __restrict__ b1,
                            const float* __restrict__ w2, const float* __restrict__ b2,
                            __nv_bfloat16* __restrict__ y1, __nv_bfloat16* __restrict__ y2) {
    int row = blockIdx.x;
    int which = blockIdx.y;
    const float* src = which ? e : x;
    const float* w   = which ? w2 : w1;
    const float* b   = which ? b2 : b1;
    __nv_bfloat16* y = which ? y2 : y1;
    int tid = threadIdx.x;
    const float4* xr = (const float4*)(src + (size_t)row * CC);
    float4 v = xr[tid];
    float s  = v.x + v.y + v.z + v.w;
    float ss = v.x*v.x + v.y*v.y + v.z*v.z + v.w*v.w;
    #pragma unroll
    for (int off = 16; off; off >>= 1) {
        s  += __shfl_xor_sync(0xffffffffu, s,  off);
        ss += __shfl_xor_sync(0xffffffffu, ss, off);
    }
    __shared__ float sm[4], sm2[4];
    int warp = tid >> 5, lane = tid & 31;
    if (lane == 0) { sm[warp] = s; sm2[warp] = ss; }
    __syncthreads();
    float tot  = sm[0] + sm[1] + sm[2] + sm[3];
    float tot2 = sm2[0] + sm2[1] + sm2[2] + sm2[3];
    float mu   = tot * (1.0f / CC);
    float var  = tot2 * (1.0f / CC) - mu * mu;
    float rstd = rsqrtf(var + 1e-5f);
    float4 wv = ((const float4*)w)[tid];
    float4 bv = ((const float4*)b)[tid];
    uint2 o;
    o.x = pack_bf16((v.x - mu) * rstd * wv.x + bv.x, (v.y - mu) * rstd * wv.y + bv.y);
    o.y = pack_bf16((v.z - mu) * rstd * wv.z + bv.z, (v.w - mu) * rstd * wv.w + bv.w);
    ((uint2*)(y + (size_t)row * CC))[tid] = o;
}

// Single-tensor LN (for LN3)
__global__ void ln_kernel(const float* __restrict__ x,
                          const float* __restrict__ w,
                          const float* __restrict__ b,
                          __nv_bfloat16* __restrict__ y) {
    int row = blockIdx.x;
    int tid = threadIdx.x;
    const float4* xr = (const float4*)(x + (size_t)row * CC);
    float4 v = xr[tid];
    float s  = v.x + v.y + v.z + v.w;
    float ss = v.x*v.x + v.y*v.y + v.z*v.z + v.w*v.w;
    #pragma unroll
    for (int off = 16; off; off >>= 1) {
        s  += __shfl_xor_sync(0xffffffffu, s,  off);
        ss += __shfl_xor_sync(0xffffffffu, ss, off);
    }
    __shared__ float sm[4], sm2[4];
    int warp = tid >> 5, lane = tid & 31;
    if (lane == 0) { sm[warp] = s; sm2[warp] = ss; }
    __syncthreads();
    float tot  = sm[0] + sm[1] + sm[2] + sm[3];
    float tot2 = sm2[0] + sm2[1] + sm2[2] + sm2[3];
    float mu   = tot * (1.0f / CC);
    float var  = tot2 * (1.0f / CC) - mu * mu;
    float rstd = rsqrtf(var + 1e-5f);
    float4 wv = ((const float4*)w)[tid];
    float4 bv = ((const float4*)b)[tid];
    uint2 o;
    o.x = pack_bf16((v.x - mu) * rstd * wv.x + bv.x, (v.y - mu) * rstd * wv.y + bv.y);
    o.y = pack_bf16((v.z - mu) * rstd * wv.z + bv.z, (v.w - mu) * rstd * wv.w + bv.w);
    ((uint2*)(y + (size_t)row * CC))[tid] = o;
}

// ---------------------------------------------------------------------------
// Uber weight-transpose: all 6 weights in one launch. Tile id -> weight.
// Tiles: wqkv 768 | wgate 256 | ws 256 | wproj 256 | wfc1 1024 | wfc2 1024 = 3584
__global__ void wt_all_kernel(
    const float* __restrict__ w_qkv, const float* __restrict__ w_gate,
    const float* __restrict__ w_s,   const float* __restrict__ w_proj,
    const float* __restrict__ w_fc1, const float* __restrict__ w_fc2,
    __nv_bfloat16* __restrict__ wqkvg, __nv_bfloat16* __restrict__ wsT,
    __nv_bfloat16* __restrict__ wpT,   __nv_bfloat16* __restrict__ wf1T,
    __nv_bfloat16* __restrict__ wf2T)
{
    __shared__ float t[32][33];
    int tb = blockIdx.x;
    const float* W; __nv_bfloat16* WT; int K, N, ntx, loc;
    if (tb < 768)       { W = w_qkv;  WT = wqkvg;                       K = 512;  N = 1536; ntx = 48; loc = tb; }
    else if (tb < 1024) { W = w_gate; WT = wqkvg + (size_t)1536 * 512;  K = 512;  N = 512;  ntx = 16; loc = tb - 768; }
    else if (tb < 1280) { W = w_s;    WT = wsT;                         K = 512;  N = 512;  ntx = 16; loc = tb - 1024; }
    else if (tb < 1536) { W = w_proj; WT = wpT;                         K = 512;  N = 512;  ntx = 16; loc = tb - 1280; }
    else if (tb < 2560) { W = w_fc1;  WT = wf1T;                        K = 512;  N = 2048; ntx = 64; loc = tb - 1536; }
    else                { W = w_fc2;  WT = wf2T;                        K = 2048; N = 512;  ntx = 16; loc = tb - 2560; }
    int n0 = (loc % ntx) * 32, k0 = (loc / ntx) * 32;
    int tx = threadIdx.x, ty = threadIdx.y;   // 32 x 8
    #pragma unroll
    for (int i = 0; i < 32; i += 8)
        t[ty + i][tx] = W[(size_t)(k0 + ty + i) * N + n0 + tx];
    __syncthreads();
    #pragma unroll
    for (int i = 0; i < 32; i += 8)
        WT[(size_t)(n0 + ty + i) * K + k0 + tx] = __float2bfloat16(t[tx][ty + i]);
}

// ---------------------------------------------------------------------------
// mm2: HMMA bf16 GEMM, 256x128 CTA tile, 64x64 warp tile, BK=32, 4-stage cp.async.
// MODE 0: fp32 out = A@Bt^T (+bias) (+res)
// MODE 1: bf16 out = gelu(A@Bt^T + bias)
// MODE 2: qkvg epilogue (N=2048): seg0 q*0.125->qh, seg1 k+s->kh, seg2 v->vh,
//         seg3 gate fp32. Per-head layouts.
#define M2_ROW  80
#define M2_B    20480           // A: 256 rows; B at row 256
#define M2_STG  30720           // 384 * 80
#define M2_NSTG 4
#define M2_SMEM (M2_NSTG * M2_STG)   // 122880

template<int MODE>
__global__ void __launch_bounds__(256) mm2_kernel(
    const __nv_bfloat16* __restrict__ A,   // [M,K]
    const __nv_bfloat16* __restrict__ Bt,  // [N,K]
    const float* __restrict__ bias,
    const float* __restrict__ res,
    const float* __restrict__ sextra,      // MODE 2: s [TT, 512]
    float* __restrict__ outf,              // MODE 0 / MODE 2 gate
    __nv_bfloat16* __restrict__ outb0,     // MODE 1 out / MODE 2 qh
    __nv_bfloat16* __restrict__ outb1,     // MODE 2 kh
    __nv_bfloat16* __restrict__ outb2,     // MODE 2 vh
    int M, int N, int K)
{
    extern __shared__ __align__(16) char smem[];
    uint32_t sb = smem_u32(smem);

    int tid = threadIdx.x, wid = tid >> 5, lane = tid & 31;
    int m0 = blockIdx.y * 256, n0 = blockIdx.x * 128;
    int wm = wid & 3, wn = wid >> 2;        // 4 x 2 warps, 64x64 each

    const char* Abase = (const char*)A;
    const char* Bbase = (const char*)Bt;
    size_t rstride = (size_t)K * 2;
    int KC = K >> 5;

    auto load_tile = [&](int kc, int stg) {
        uint32_t base = sb + stg * M2_STG;
        size_t koff = (size_t)kc * 64;
        #pragma unroll
        for (int i = 0; i < 6; i++) {
            int idx = i * 256 + tid;         // 0..1535
            int row = idx >> 2;              // 0..383
            int c = (idx & 3) * 16;
            const char* g = (row < 256)
                ? Abase + (size_t)(m0 + row) * rstride + koff + c
                : Bbase + (size_t)(n0 + row - 256) * rstride + koff + c;
            cp_async16(base + row * M2_ROW + c, g);
        }
        cp_commit();
    };

    float acc[4][8][4];
    #pragma unroll
    for (int mi = 0; mi < 4; mi++)
        #pragma unroll
        for (int nb = 0; nb < 8; nb++)
            #pragma unroll
            for (int j = 0; j < 4; j++) acc[mi][nb][j] = 0.f;

    load_tile(0, 0);
    load_tile(1, 1);
    load_tile(2, 2);

    uint32_t lrow16 = (lane & 15);
    uint32_t lkhalf = (lane >> 4) * 16;

    for (int kc = 0; kc < KC; kc++) {
        if (kc < KC - 2)      asm volatile("cp.async.wait_group 2;" ::: "memory");
        else if (kc == KC - 2) asm volatile("cp.async.wait_group 1;" ::: "memory");
        else                   asm volatile("cp.async.wait_group 0;" ::: "memory");
        __syncthreads();

        if (kc + 3 < KC) load_tile(kc + 3, (kc + 3) & (M2_NSTG - 1));

        int stg = kc & (M2_NSTG - 1);
        uint32_t sA = sb + stg * M2_STG + (wm * 64 + lrow16) * M2_ROW + lkhalf;
        uint32_t sB = sb + stg * M2_STG + M2_B + (wn * 64 + lrow16) * M2_ROW + lkhalf;

        #pragma unroll
        for (int ks = 0; ks < 2; ks++) {
            uint32_t koff = ks * 32;
            uint32_t a[4][4];
            #pragma unroll
            for (int mi = 0; mi < 4; mi++)
                ldmx4(a[mi][0], a[mi][1], a[mi][2], a[mi][3],
                      sA + mi * 16 * M2_ROW + koff);
            uint32_t b[4][4];
            #pragma unroll
            for (int nb = 0; nb < 4; nb++)
                ldmx4(b[nb][0], b[nb][1], b[nb][2], b[nb][3],
                      sB + nb * 16 * M2_ROW + koff);
            #pragma unroll
            for (int mi = 0; mi < 4; mi++)
                #pragma unroll
                for (int nb = 0; nb < 4; nb++) {
                    mma16816(acc[mi][nb * 2 + 0], a[mi], b[nb][0], b[nb][2]);
                    mma16816(acc[mi][nb * 2 + 1], a[mi], b[nb][1], b[nb][3]);
                }
        }
    }

    // ---- epilogue ----
    int mbase = m0 + wm * 64 + (lane >> 2);
    int nbase = n0 + wn * 64 + (lane & 3) * 2;
    int seg = nbase >> 9;          // uniform per warp (MODE 2)

    #pragma unroll
    for (int mi = 0; mi < 4; mi++) {
        #pragma unroll
        for (int nb = 0; nb < 8; nb++) {
            int n = nbase + nb * 8;
            #pragma unroll
            for (int half = 0; half < 2; half++) {
                int m = mbase + mi * 16 + half * 8;
                float v0 = acc[mi][nb][half * 2 + 0];
                float v1 = acc[mi][nb][half * 2 + 1];
                if (MODE == 0) {
                    if (bias) { v0 += bias[n]; v1 += bias[n + 1]; }
                    if (res) {
                        const float* rp = res + (size_t)m * N + n;
                        v0 += rp[0]; v1 += rp[1];
                    }
                    *(float2*)(outf + (size_t)m * N + n) = make_float2(v0, v1);
                } else if (MODE == 1) {
                    v0 += bias[n]; v1 += bias[n + 1];
                    v0 = 0.5f * v0 * (1.0f + erff(v0 * 0.70710678118654752f));
                    v1 = 0.5f * v1 * (1.0f + erff(v1 * 0.70710678118654752f));
                    *(uint32_t*)(outb0 + (size_t)m * N + n) = pack_bf16(v0, v1);
                } else {
                    int c = n & 511;
                    int bidx = m >> 11, nloc = m & (NN - 1);
                    if (seg == 3) {
                        *(float2*)(outf + (size_t)m * CC + c) = make_float2(v0, v1);
                    } else {
                        int h = c >> 6, d = c & 63;
                        size_t ph = (((size_t)(bidx * HH + h) * NN + nloc) << 6) + d;
                        if (seg == 0) {
                            *(uint32_t*)(outb0 + ph) = pack_bf16(v0 * 0.125f, v1 * 0.125f);
                        } else if (seg == 1) {
                            float2 sv = *(const float2*)(sextra + (size_t)m * CC + c);
                            *(uint32_t*)(outb1 + ph) = pack_bf16(v0 + sv.x, v1 + sv.y);
                        } else {
                            *(uint32_t*)(outb2 + ph) = pack_bf16(v0, v1);
                        }
                    }
                }
            }
        }
    }
}

// ---------------------------------------------------------------------------
// bf16 HMMA flash attention, fused gate-multiply epilogue.
#define AT_QOFF 0
#define AT_ROW  144
#define AT_KV0  18432
#define AT_STG  18432
#define AT_SMEM (18432 + 2 * 18432)

__global__ void __launch_bounds__(256) attn_kernel(
    const __nv_bfloat16* __restrict__ qh,
    const __nv_bfloat16* __restrict__ kh,
    const __nv_bfloat16* __restrict__ vh,
    const float* __restrict__ gate,
    __nv_bfloat16* __restrict__ outb)
{
    extern __shared__ char smem[];
    uint32_t sb = smem_u32(smem);
    int tid = threadIdx.x, wid = tid >> 5, lane = tid & 31;
    int qt = blockIdx.x, h = blockIdx.y, b = blockIdx.z;
    int bh = b * HH + h;
    int tq0 = qt * 128;

    const char* Qg = (const char*)(qh + (((size_t)bh * NN + tq0) << 6));
    const char* Kg = (const char*)(kh + ((size_t)bh * NN << 6));
    const char* Vg = (const char*)(vh + ((size_t)bh * NN << 6));

    for (int i = tid; i < 1024; i += 256) {
        int r = i >> 3, c = (i & 7) * 16;
        cp_async16(sb + AT_QOFF + r * AT_ROW + c, Qg + (size_t)r * 128 + c);
    }
    cp_commit();

    auto loadKV = [&](int kt, int stg) {
        const char* K0 = Kg + ((size_t)kt << 13);
        const char* V0 = Vg + ((size_t)kt << 13);
        uint32_t ks = sb + AT_KV0 + stg * AT_STG;
        for (int i = tid; i < 512; i += 256) {
            int r = i >> 3, c = (i & 7) * 16;
            cp_async16(ks + r * AT_ROW + c, K0 + (size_t)r * 128 + c);
            cp_async16(ks + 9216 + r * AT_ROW + c, V0 + (size_t)r * 128 + c);
        }
        cp_commit();
    };

    loadKV(0, 0);
    asm volatile("cp.async.wait_group 0;" ::: "memory");
    __syncthreads();

    int r0 = wid * 16;
    uint32_t qf[4][4];
    {
        uint32_t base = sb + AT_QOFF + (r0 + (lane & 15)) * AT_ROW + (lane >> 4) * 16;
        #pragma unroll
        for (int kb = 0; kb < 4; kb++)
            ldmx4(qf[kb][0], qf[kb][1], qf[kb][2], qf[kb][3], base + kb * 32);
    }

    float o[8][4];
    #pragma unroll
    for (int nd = 0; nd < 8; nd++)
        #pragma unroll
        for (int j = 0; j < 4; j++) o[nd][j] = 0.f;
    float m0 = -1e30f, m1 = -1e30f, l0 = 0.f, l1 = 0.f;

    const int KT = NN / 64;
    for (int kt = 0; kt < KT; kt++) {
        int stg = kt & 1;
        if (kt + 1 < KT) {
            loadKV(kt + 1, stg ^ 1);
            asm volatile("cp.async.wait_group 1;" ::: "memory");
        } else {
            asm volatile("cp.async.wait_group 0;" ::: "memory");
        }
        __syncthreads();

        uint32_t Kst = sb + AT_KV0 + stg * AT_STG;
        uint32_t Vst = Kst + 9216;

        float sc[8][4];
        #pragma unroll
        for (int nb = 0; nb < 8; nb++)
            #pragma unroll
            for (int j = 0; j < 4; j++) sc[nb][j] = 0.f;

        int j2 = lane >> 3;
        int rin = lane & 7;
        #pragma unroll
        for (int p = 0; p < 4; p++) {
            #pragma unroll
            for (int kb = 0; kb < 4; kb++) {
                uint32_t addr = Kst + (p * 16 + (j2 >> 1) * 8 + rin) * AT_ROW
                                    + kb * 32 + (j2 & 1) * 16;
                uint32_t b0, b1, b2, b3;
                ldmx4(b0, b1, b2, b3, addr);
                mma16816(sc[2 * p + 0], qf[kb], b0, b1);
                mma16816(sc[2 * p + 1], qf[kb], b2, b3);
            }
        }

        float mx0 = -1e30f, mx1 = -1e30f;
        #pragma unroll
        for (int nb = 0; nb < 8; nb++) {
            mx0 = fmaxf(mx0, fmaxf(sc[nb][0], sc[nb][1]));
            mx1 = fmaxf(mx1, fmaxf(sc[nb][2], sc[nb][3]));
        }
        mx0 = fmaxf(mx0, __shfl_xor_sync(0xffffffffu, mx0, 1));
        mx0 = fmaxf(mx0, __shfl_xor_sync(0xffffffffu, mx0, 2));
        mx1 = fmaxf(mx1, __shfl_xor_sync(0xffffffffu, mx1, 1));
        mx1 = fmaxf(mx1, __shfl_xor_sync(0xffffffffu, mx1, 2));

        float mn0 = fmaxf(m0, mx0), mn1 = fmaxf(m1, mx1);
        float corr0 = __expf(m0 - mn0), corr1 = __expf(m1 - mn1);
        m0 = mn0; m1 = mn1;

        uint32_t pa[8], pb[8];
        float sum0 = 0.f, sum1 = 0.f;
        #pragma unroll
        for (int nb = 0; nb < 8; nb++) {
            float p0 = __expf(sc[nb][0] - mn0);
            float p1 = __expf(sc[nb][1] - mn0);
            float p2 = __expf(sc[nb][2] - mn1);
            float p3 = __expf(sc[nb][3] - mn1);
            sum0 += p0 + p1; sum1 += p2 + p3;
            pa[nb] = pack_bf16(p0, p1);
            pb[nb] = pack_bf16(p2, p3);
        }
        sum0 += __shfl_xor_sync(0xffffffffu, sum0, 1);
        sum0 += __shfl_xor_sync(0xffffffffu, sum0, 2);
        sum1 += __shfl_xor_sync(0xffffffffu, sum1, 1);
        sum1 += __shfl_xor_sync(0xffffffffu, sum1, 2);
        l0 = l0 * corr0 + sum0;
        l1 = l1 * corr1 + sum1;

        #pragma unroll
        for (int nd = 0; nd < 8; nd++) {
            o[nd][0] *= corr0; o[nd][1] *= corr0;
            o[nd][2] *= corr1; o[nd][3] *= corr1;
        }

        #pragma unroll
        for (int kb = 0; kb < 4; kb++) {
            uint32_t a[4] = { pa[2 * kb], pb[2 * kb], pa[2 * kb + 1], pb[2 * kb + 1] };
            #pragma unroll
            for (int v = 0; v < 4; v++) {
                uint32_t addr = Vst + (kb * 16 + (j2 & 1) * 8 + rin) * AT_ROW
                                    + v * 32 + (j2 >> 1) * 16;
                uint32_t b0, b1, b2, b3;
                ldmx4t(b0, b1, b2, b3, addr);
                mma16816(o[2 * v + 0], a, b0, b1);
                mma16816(o[2 * v + 1], a, b2, b3);
            }
        }
        __syncthreads();
    }

    float inv0 = 1.0f / l0, inv1 = 1.0f / l1;
    int rowa = tq0 + r0 + (lane >> 2);
    size_t toka = (size_t)b * NN + rowa;
    size_t tokb = toka + 8;
    int cb = h * DD + (lane & 3) * 2;
    #pragma unroll
    for (int nd = 0; nd < 8; nd++) {
        int d = cb + nd * 8;
        float2 ga = *(const float2*)(gate + toka * CC + d);
        float2 gb = *(const float2*)(gate + tokb * CC + d);
        *(uint32_t*)(outb + toka * CC + d) = pack_bf16(o[nd][0] * inv0 * ga.x,
                                                       o[nd][1] * inv0 * ga.y);
        *(uint32_t*)(outb + tokb * CC + d) = pack_bf16(o[nd][2] * inv1 * gb.x,
                                                       o[nd][3] * inv1 * gb.y);
    }
}

// ---------------------------------------------------------------------------
extern "C" void kernel_launch(void* const* d_in, const int* in_sizes, int n_in,
                              void* d_out, int out_size) {
    const float* x      = (const float*)d_in[0];
    const float* e      = (const float*)d_in[1];
    const float* w_qkv  = (const float*)d_in[2];
    const float* w_s    = (const float*)d_in[3];
    const float* w_gate = (const float*)d_in[4];
    const float* w_proj = (const float*)d_in[5];
    const float* b_proj = (const float*)d_in[6];
    const float* ln1_w  = (const float*)d_in[7];
    const float* ln1_b  = (const float*)d_in[8];
    const float* ln2_w  = (const float*)d_in[9];
    const float* ln2_b  = (const float*)d_in[10];
    const float* ln3_w  = (const float*)d_in[11];
    const float* ln3_b  = (const float*)d_in[12];
    const float* w_fc1  = (const float*)d_in[13];
    const float* b_fc1  = (const float*)d_in[14];
    const float* w_fc2  = (const float*)d_in[15];
    const float* b_fc2  = (const float*)d_in[16];
    float* out = (float*)d_out;

    void* scr_v = nullptr;
    cudaGetSymbolAddress(&scr_v, g_scratch);
    float* scr = (float*)scr_v;
    float*         g_s    = scr + OFF_S;
    float*         g_gate = scr + OFF_GATE;
    float*         g_x1   = scr + OFF_X1;
    __nv_bfloat16* g_xnb  = (__nv_bfloat16*)(scr + OFF_XNB);
    __nv_bfloat16* g_enb  = (__nv_bfloat16*)(scr + OFF_ENB);
    __nv_bfloat16* g_xn3b = (__nv_bfloat16*)(scr + OFF_XN3B);
    __nv_bfloat16* g_agb  = (__nv_bfloat16*)(scr + OFF_AGB);
    __nv_bfloat16* g_hb   = (__nv_bfloat16*)(scr + OFF_HB);
    __nv_bfloat16* wqkvg  = (__nv_bfloat16*)(scr + OFF_WQKVG);
    __nv_bfloat16* wsT    = (__nv_bfloat16*)(scr + OFF_WST);
    __nv_bfloat16* wpT    = (__nv_bfloat16*)(scr + OFF_WPT);
    __nv_bfloat16* wf1T   = (__nv_bfloat16*)(scr + OFF_WF1T);
    __nv_bfloat16* wf2T   = (__nv_bfloat16*)(scr + OFF_WF2T);
    __nv_bfloat16* g_qh   = (__nv_bfloat16*)(scr + OFF_QH);
    __nv_bfloat16* g_kh   = (__nv_bfloat16*)(scr + OFF_KH);
    __nv_bfloat16* g_vh   = (__nv_bfloat16*)(scr + OFF_VH);

    cudaFuncSetAttribute(attn_kernel, cudaFuncAttributeMaxDynamicSharedMemorySize, AT_SMEM);
    cudaFuncSetAttribute(mm2_kernel<0>, cudaFuncAttributeMaxDynamicSharedMemorySize, M2_SMEM);
    cudaFuncSetAttribute(mm2_kernel<1>, cudaFuncAttributeMaxDynamicSharedMemorySize, M2_SMEM);
    cudaFuncSetAttribute(mm2_kernel<2>, cudaFuncAttributeMaxDynamicSharedMemorySize, M2_SMEM);

    // all weight transposes in one launch
    wt_all_kernel<<<3584, dim3(32, 8)>>>(w_qkv, w_gate, w_s, w_proj, w_fc1, w_fc2,
                                         wqkvg, wsT, wpT, wf1T, wf2T);

    // LN1(x) and LN2(e) in one launch
    ln2x_kernel<<<dim3(TT, 2), 128>>>(x, e, ln1_w, ln1_b, ln2_w, ln2_b, g_xnb, g_enb);

    // s = en @ w_s  (fp32, needed by qkvg epilogue)
    mm2_kernel<0><<<dim3(CC / 128, TT / 256), 256, M2_SMEM>>>(
        g_enb, wsT, nullptr, nullptr, nullptr, g_s, nullptr, nullptr, nullptr,
        TT, CC, CC);

    // fused qkv+gate GEMM with per-head scatter epilogue
    mm2_kernel<2><<<dim3(2048 / 128, TT / 256), 256, M2_SMEM>>>(
        g_xnb, wqkvg, nullptr, nullptr, g_s, g_gate, g_qh, g_kh, g_vh,
        TT, 2048, CC);

    attn_kernel<<<dim3(NN / 128, HH, BB), 256, AT_SMEM>>>(g_qh, g_kh, g_vh, g_gate, g_agb);

    // x1 = x + ag @ w_proj + b_proj
    mm2_kernel<0><<<dim3(CC / 128, TT / 256), 256, M2_SMEM>>>(
        g_agb, wpT, b_proj, x, nullptr, g_x1, nullptr, nullptr, nullptr,
        TT, CC, CC);

    ln_kernel<<<TT, 128>>>(g_x1, ln3_w, ln3_b, g_xn3b);

    // h = gelu(xn3 @ w_fc1 + b_fc1) -> bf16
    mm2_kernel<1><<<dim3(FF / 128, TT / 256), 256, M2_SMEM>>>(
        g_xn3b, wf1T, b_fc1, nullptr, nullptr, nullptr, g_hb, nullptr, nullptr,
        TT, FF, CC);

    // out = x1 + h @ w_fc2 + b_fc2
    mm2_kernel<0><<<dim3(CC / 128, TT / 256), 256, M2_SMEM>>>(
        g_hb, wf2T, b_fc2, g_x1, nullptr, out, nullptr, nullptr, nullptr,
        TT, CC, FF);
}

// round 11
// speedup vs baseline: 6.7709x; 1.0712x over previous
#include <cuda_runtime.h>
#include <cuda_bf16.h>
#include <math.h>
#include <cstdint>

// Problem constants
#define BB 4
#define NN 2048
#define CC 512
#define HH 8
#define DD 64
#define TT (BB*NN)          // 8192 tokens
#define FF 2048             // d_ff

// ---------------------------------------------------------------------------
// Scratch layout (float units)
#define OFF_S     0ull          // fp32 [TT, C]
#define OFF_GATE  4194304ull    // fp32 [TT, C]
#define OFF_X1    8388608ull    // fp32 [TT, C]
#define OFF_XNB   12582912ull   // bf16 [TT, C]
#define OFF_ENB   14680064ull   // bf16 [TT, C]
#define OFF_XN3B  16777216ull   // bf16 [TT, C]
#define OFF_AGB   18874368ull   // bf16 [TT, C]
#define OFF_HB    20971520ull   // bf16 [TT, FF]
#define OFF_WQKVG 29360128ull   // bf16 [2048, 512]  (rows: wqkvT 0..1535, wgT 1536..2047)
#define OFF_WST   29884416ull   // bf16 [C, C]
#define OFF_WPT   30015488ull   // bf16 [C, C]
#define OFF_WF1T  30146560ull   // bf16 [FF, C]
#define OFF_WF2T  30670848ull   // bf16 [C, FF]
#define OFF_QH    31195136ull   // bf16 [B*H, N, 64]
#define OFF_KH    33292288ull   // bf16 [B*H, N, 64]
#define OFF_VH    35389440ull   // bf16 [B*H, N, 64]
#define SCRATCH_FLOATS 37486592ull

__device__ float g_scratch[SCRATCH_FLOATS];

// ---------------------------------------------------------------------------
__device__ __forceinline__ uint32_t smem_u32(const void* p) {
    uint32_t a;
    asm("{ .reg .u64 t; cvta.to.shared.u64 t, %1; cvt.u32.u64 %0, t; }" : "=r"(a) : "l"(p));
    return a;
}
__device__ __forceinline__ void cp_async16(uint32_t saddr, const void* gaddr) {
    asm volatile("cp.async.cg.shared.global [%0], [%1], 16;" :: "r"(saddr), "l"(gaddr) : "memory");
}
__device__ __forceinline__ void cp_commit() {
    asm volatile("cp.async.commit_group;" ::: "memory");
}
__device__ __forceinline__ void ldmx4(uint32_t& r0, uint32_t& r1, uint32_t& r2, uint32_t& r3,
                                      uint32_t addr) {
    asm volatile("ldmatrix.sync.aligned.m8n8.x4.shared.b16 {%0,%1,%2,%3}, [%4];"
                 : "=r"(r0), "=r"(r1), "=r"(r2), "=r"(r3) : "r"(addr));
}
__device__ __forceinline__ void ldmx4t(uint32_t& r0, uint32_t& r1, uint32_t& r2, uint32_t& r3,
                                       uint32_t addr) {
    asm volatile("ldmatrix.sync.aligned.m8n8.x4.trans.shared.b16 {%0,%1,%2,%3}, [%4];"
                 : "=r"(r0), "=r"(r1), "=r"(r2), "=r"(r3) : "r"(addr));
}
__device__ __forceinline__ void mma16816(float* c, const uint32_t* a, uint32_t b0, uint32_t b1) {
    asm volatile(
        "mma.sync.aligned.m16n8k16.row.col.f32.bf16.bf16.f32 "
        "{%0,%1,%2,%3}, {%4,%5,%6,%7}, {%8,%9}, {%0,%1,%2,%3};"
        : "+f"(c[0]), "+f"(c[1]), "+f"(c[2]), "+f"(c[3])
        : "r"(a[0]), "r"(a[1]), "r"(a[2]), "r"(a[3]), "r"(b0), "r"(b1));
}
__device__ __forceinline__ uint32_t pack_bf16(float a, float b) {
    __nv_bfloat162 p = __floats2bfloat162_rn(a, b);
    return *(uint32_t*)&p;
}

// ---------------------------------------------------------------------------
// Fused LayerNorm for LN1(x) and LN2(e): blockIdx.y selects.
__global__ void ln2x_kernel(const float* __restrict__ x, const float* __restrict__ e,
                            const float* __restrict__ w1, const float* __restrict__ b1,
                            const float* __restrict__ w2, const float* __restrict__ b2,
                            __nv_bfloat16* __restrict__ y1, __nv_bfloat16* __restrict__ y2) {
    int row = blockIdx.x;
    int which = blockIdx.y;
    const float* src = which ? e : x;
    const float* w   = which ? w2 : w1;
    const float* b   = which ? b2 : b1;
    __nv_bfloat16* y = which ? y2 : y1;
    int tid = threadIdx.x;
    const float4* xr = (const float4*)(src + (size_t)row * CC);
    float4 v = xr[tid];
    float s  = v.x + v.y + v.z + v.w;
    float ss = v.x*v.x + v.y*v.y + v.z*v.z + v.w*v.w;
    #pragma unroll
    for (int off = 16; off; off >>= 1) {
        s  += __shfl_xor_sync(0xffffffffu, s,  off);
        ss += __shfl_xor_sync(0xffffffffu, ss, off);
    }
    __shared__ float sm[4], sm2[4];
    int warp = tid >> 5, lane = tid & 31;
    if (lane == 0) { sm[warp] = s; sm2[warp] = ss; }
    __syncthreads();
    float tot  = sm[0] + sm[1] + sm[2] + sm[3];
    float tot2 = sm2[0] + sm2[1] + sm2[2] + sm2[3];
    float mu   = tot * (1.0f / CC);
    float var  = tot2 * (1.0f / CC) - mu * mu;
    float rstd = rsqrtf(var + 1e-5f);
    float4 wv = ((const float4*)w)[tid];
    float4 bv = ((const float4*)b)[tid];
    uint2 o;
    o.x = pack_bf16((v.x - mu) * rstd * wv.x + bv.x, (v.y - mu) * rstd * wv.y + bv.y);
    o.y = pack_bf16((v.z - mu) * rstd * wv.z + bv.z, (v.w - mu) * rstd * wv.w + bv.w);
    ((uint2*)(y + (size_t)row * CC))[tid] = o;
}

// Single-tensor LN (for LN3)
__global__ void ln_kernel(const float* __restrict__ x,
                          const float* __restrict__ w,
                          const float* __restrict__ b,
                          __nv_bfloat16* __restrict__ y) {
    int row = blockIdx.x;
    int tid = threadIdx.x;
    const float4* xr = (const float4*)(x + (size_t)row * CC);
    float4 v = xr[tid];
    float s  = v.x + v.y + v.z + v.w;
    float ss = v.x*v.x + v.y*v.y + v.z*v.z + v.w*v.w;
    #pragma unroll
    for (int off = 16; off; off >>= 1) {
        s  += __shfl_xor_sync(0xffffffffu, s,  off);
        ss += __shfl_xor_sync(0xffffffffu, ss, off);
    }
    __shared__ float sm[4], sm2[4];
    int warp = tid >> 5, lane = tid & 31;
    if (lane == 0) { sm[warp] = s; sm2[warp] = ss; }
    __syncthreads();
    float tot  = sm[0] + sm[1] + sm[2] + sm[3];
    float tot2 = sm2[0] + sm2[1] + sm2[2] + sm2[3];
    float mu   = tot * (1.0f / CC);
    float var  = tot2 * (1.0f / CC) - mu * mu;
    float rstd = rsqrtf(var + 1e-5f);
    float4 wv = ((const float4*)w)[tid];
    float4 bv = ((const float4*)b)[tid];
    uint2 o;
    o.x = pack_bf16((v.x - mu) * rstd * wv.x + bv.x, (v.y - mu) * rstd * wv.y + bv.y);
    o.y = pack_bf16((v.z - mu) * rstd * wv.z + bv.z, (v.w - mu) * rstd * wv.w + bv.w);
    ((uint2*)(y + (size_t)row * CC))[tid] = o;
}

// ---------------------------------------------------------------------------
// Uber weight-transpose: all 6 weights in one launch. Tile id -> weight.
__global__ void wt_all_kernel(
    const float* __restrict__ w_qkv, const float* __restrict__ w_gate,
    const float* __restrict__ w_s,   const float* __restrict__ w_proj,
    const float* __restrict__ w_fc1, const float* __restrict__ w_fc2,
    __nv_bfloat16* __restrict__ wqkvg, __nv_bfloat16* __restrict__ wsT,
    __nv_bfloat16* __restrict__ wpT,   __nv_bfloat16* __restrict__ wf1T,
    __nv_bfloat16* __restrict__ wf2T)
{
    __shared__ float t[32][33];
    int tb = blockIdx.x;
    const float* W; __nv_bfloat16* WT; int K, N, ntx, loc;
    if (tb < 768)       { W = w_qkv;  WT = wqkvg;                       K = 512;  N = 1536; ntx = 48; loc = tb; }
    else if (tb < 1024) { W = w_gate; WT = wqkvg + (size_t)1536 * 512;  K = 512;  N = 512;  ntx = 16; loc = tb - 768; }
    else if (tb < 1280) { W = w_s;    WT = wsT;                         K = 512;  N = 512;  ntx = 16; loc = tb - 1024; }
    else if (tb < 1536) { W = w_proj; WT = wpT;                         K = 512;  N = 512;  ntx = 16; loc = tb - 1280; }
    else if (tb < 2560) { W = w_fc1;  WT = wf1T;                        K = 512;  N = 2048; ntx = 64; loc = tb - 1536; }
    else                { W = w_fc2;  WT = wf2T;                        K = 2048; N = 512;  ntx = 16; loc = tb - 2560; }
    int n0 = (loc % ntx) * 32, k0 = (loc / ntx) * 32;
    int tx = threadIdx.x, ty = threadIdx.y;   // 32 x 8
    #pragma unroll
    for (int i = 0; i < 32; i += 8)
        t[ty + i][tx] = W[(size_t)(k0 + ty + i) * N + n0 + tx];
    __syncthreads();
    #pragma unroll
    for (int i = 0; i < 32; i += 8)
        WT[(size_t)(n0 + ty + i) * K + k0 + tx] = __float2bfloat16(t[tx][ty + i]);
}

// ---------------------------------------------------------------------------
// mm2: HMMA bf16 GEMM, 256x128 CTA tile, 512 threads (16 warps, 4x4 grid,
// 64x32 warp tiles), BK=32, 4-stage cp.async.
// MODE 0: fp32 out = A@Bt^T (+bias) (+res)
// MODE 1: bf16 out = gelu(A@Bt^T + bias)
// MODE 2: qkvg epilogue (N=2048): seg0 q*0.125->qh, seg1 k+s->kh, seg2 v->vh,
//         seg3 gate fp32. Per-head layouts.
#define M2_ROW  80
#define M2_B    20480           // A: 256 rows; B at row 256
#define M2_STG  30720           // 384 * 80
#define M2_NSTG 4
#define M2_SMEM (M2_NSTG * M2_STG)   // 122880

template<int MODE>
__global__ void __launch_bounds__(512) mm2_kernel(
    const __nv_bfloat16* __restrict__ A,   // [M,K]
    const __nv_bfloat16* __restrict__ Bt,  // [N,K]
    const float* __restrict__ bias,
    const float* __restrict__ res,
    const float* __restrict__ sextra,      // MODE 2: s [TT, 512]
    float* __restrict__ outf,              // MODE 0 / MODE 2 gate
    __nv_bfloat16* __restrict__ outb0,     // MODE 1 out / MODE 2 qh
    __nv_bfloat16* __restrict__ outb1,     // MODE 2 kh
    __nv_bfloat16* __restrict__ outb2,     // MODE 2 vh
    int M, int N, int K)
{
    extern __shared__ __align__(16) char smem[];
    uint32_t sb = smem_u32(smem);

    int tid = threadIdx.x, wid = tid >> 5, lane = tid & 31;
    int m0 = blockIdx.y * 256, n0 = blockIdx.x * 128;
    int wm = wid & 3, wn = wid >> 2;        // 4 x 4 warps, 64x32 each

    const char* Abase = (const char*)A;
    const char* Bbase = (const char*)Bt;
    size_t rstride = (size_t)K * 2;
    int KC = K >> 5;

    auto load_tile = [&](int kc, int stg) {
        uint32_t base = sb + stg * M2_STG;
        size_t koff = (size_t)kc * 64;
        #pragma unroll
        for (int i = 0; i < 3; i++) {
            int idx = i * 512 + tid;         // 0..1535
            int row = idx >> 2;              // 0..383
            int c = (idx & 3) * 16;
            const char* g = (row < 256)
                ? Abase + (size_t)(m0 + row) * rstride + koff + c
                : Bbase + (size_t)(n0 + row - 256) * rstride + koff + c;
            cp_async16(base + row * M2_ROW + c, g);
        }
        cp_commit();
    };

    float acc[4][4][4];
    #pragma unroll
    for (int mi = 0; mi < 4; mi++)
        #pragma unroll
        for (int nb = 0; nb < 4; nb++)
            #pragma unroll
            for (int j = 0; j < 4; j++) acc[mi][nb][j] = 0.f;

    load_tile(0, 0);
    load_tile(1, 1);
    load_tile(2, 2);

    uint32_t lrow16 = (lane & 15);
    uint32_t lkhalf = (lane >> 4) * 16;

    for (int kc = 0; kc < KC; kc++) {
        if (kc < KC - 2)      asm volatile("cp.async.wait_group 2;" ::: "memory");
        else if (kc == KC - 2) asm volatile("cp.async.wait_group 1;" ::: "memory");
        else                   asm volatile("cp.async.wait_group 0;" ::: "memory");
        __syncthreads();

        if (kc + 3 < KC) load_tile(kc + 3, (kc + 3) & (M2_NSTG - 1));

        int stg = kc & (M2_NSTG - 1);
        uint32_t sA = sb + stg * M2_STG + (wm * 64 + lrow16) * M2_ROW + lkhalf;
        uint32_t sB = sb + stg * M2_STG + M2_B + (wn * 32 + lrow16) * M2_ROW + lkhalf;

        #pragma unroll
        for (int ks = 0; ks < 2; ks++) {
            uint32_t koff = ks * 32;
            uint32_t a[4][4];
            #pragma unroll
            for (int mi = 0; mi < 4; mi++)
                ldmx4(a[mi][0], a[mi][1], a[mi][2], a[mi][3],
                      sA + mi * 16 * M2_ROW + koff);
            uint32_t b[2][4];
            #pragma unroll
            for (int nb = 0; nb < 2; nb++)
                ldmx4(b[nb][0], b[nb][1], b[nb][2], b[nb][3],
                      sB + nb * 16 * M2_ROW + koff);
            #pragma unroll
            for (int mi = 0; mi < 4; mi++)
                #pragma unroll
                for (int nb = 0; nb < 2; nb++) {
                    mma16816(acc[mi][nb * 2 + 0], a[mi], b[nb][0], b[nb][2]);
                    mma16816(acc[mi][nb * 2 + 1], a[mi], b[nb][1], b[nb][3]);
                }
        }
    }

    // ---- epilogue ----
    int mbase = m0 + wm * 64 + (lane >> 2);
    int nbase = n0 + wn * 32 + (lane & 3) * 2;
    int seg = nbase >> 9;          // uniform per warp (MODE 2)

    #pragma unroll
    for (int mi = 0; mi < 4; mi++) {
        #pragma unroll
        for (int nb = 0; nb < 4; nb++) {
            int n = nbase + nb * 8;
            #pragma unroll
            for (int half = 0; half < 2; half++) {
                int m = mbase + mi * 16 + half * 8;
                float v0 = acc[mi][nb][half * 2 + 0];
                float v1 = acc[mi][nb][half * 2 + 1];
                if (MODE == 0) {
                    if (bias) { v0 += bias[n]; v1 += bias[n + 1]; }
                    if (res) {
                        const float* rp = res + (size_t)m * N + n;
                        v0 += rp[0]; v1 += rp[1];
                    }
                    *(float2*)(outf + (size_t)m * N + n) = make_float2(v0, v1);
                } else if (MODE == 1) {
                    v0 += bias[n]; v1 += bias[n + 1];
                    v0 = 0.5f * v0 * (1.0f + erff(v0 * 0.70710678118654752f));
                    v1 = 0.5f * v1 * (1.0f + erff(v1 * 0.70710678118654752f));
                    *(uint32_t*)(outb0 + (size_t)m * N + n) = pack_bf16(v0, v1);
                } else {
                    int c = n & 511;
                    int bidx = m >> 11, nloc = m & (NN - 1);
                    if (seg == 3) {
                        *(float2*)(outf + (size_t)m * CC + c) = make_float2(v0, v1);
                    } else {
                        int h = c >> 6, d = c & 63;
                        size_t ph = (((size_t)(bidx * HH + h) * NN + nloc) << 6) + d;
                        if (seg == 0) {
                            *(uint32_t*)(outb0 + ph) = pack_bf16(v0 * 0.125f, v1 * 0.125f);
                        } else if (seg == 1) {
                            float2 sv = *(const float2*)(sextra + (size_t)m * CC + c);
                            *(uint32_t*)(outb1 + ph) = pack_bf16(v0 + sv.x, v1 + sv.y);
                        } else {
                            *(uint32_t*)(outb2 + ph) = pack_bf16(v0, v1);
                        }
                    }
                }
            }
        }
    }
}

// ---------------------------------------------------------------------------
// bf16 HMMA flash attention, fused gate-multiply epilogue.
#define AT_QOFF 0
#define AT_ROW  144
#define AT_KV0  18432
#define AT_STG  18432
#define AT_SMEM (18432 + 2 * 18432)

__global__ void __launch_bounds__(256) attn_kernel(
    const __nv_bfloat16* __restrict__ qh,
    const __nv_bfloat16* __restrict__ kh,
    const __nv_bfloat16* __restrict__ vh,
    const float* __restrict__ gate,
    __nv_bfloat16* __restrict__ outb)
{
    extern __shared__ char smem[];
    uint32_t sb = smem_u32(smem);
    int tid = threadIdx.x, wid = tid >> 5, lane = tid & 31;
    int qt = blockIdx.x, h = blockIdx.y, b = blockIdx.z;
    int bh = b * HH + h;
    int tq0 = qt * 128;

    const char* Qg = (const char*)(qh + (((size_t)bh * NN + tq0) << 6));
    const char* Kg = (const char*)(kh + ((size_t)bh * NN << 6));
    const char* Vg = (const char*)(vh + ((size_t)bh * NN << 6));

    for (int i = tid; i < 1024; i += 256) {
        int r = i >> 3, c = (i & 7) * 16;
        cp_async16(sb + AT_QOFF + r * AT_ROW + c, Qg + (size_t)r * 128 + c);
    }
    cp_commit();

    auto loadKV = [&](int kt, int stg) {
        const char* K0 = Kg + ((size_t)kt << 13);
        const char* V0 = Vg + ((size_t)kt << 13);
        uint32_t ks = sb + AT_KV0 + stg * AT_STG;
        for (int i = tid; i < 512; i += 256) {
            int r = i >> 3, c = (i & 7) * 16;
            cp_async16(ks + r * AT_ROW + c, K0 + (size_t)r * 128 + c);
            cp_async16(ks + 9216 + r * AT_ROW + c, V0 + (size_t)r * 128 + c);
        }
        cp_commit();
    };

    loadKV(0, 0);
    asm volatile("cp.async.wait_group 0;" ::: "memory");
    __syncthreads();

    int r0 = wid * 16;
    uint32_t qf[4][4];
    {
        uint32_t base = sb + AT_QOFF + (r0 + (lane & 15)) * AT_ROW + (lane >> 4) * 16;
        #pragma unroll
        for (int kb = 0; kb < 4; kb++)
            ldmx4(qf[kb][0], qf[kb][1], qf[kb][2], qf[kb][3], base + kb * 32);
    }

    float o[8][4];
    #pragma unroll
    for (int nd = 0; nd < 8; nd++)
        #pragma unroll
        for (int j = 0; j < 4; j++) o[nd][j] = 0.f;
    float m0 = -1e30f, m1 = -1e30f, l0 = 0.f, l1 = 0.f;

    const int KT = NN / 64;
    for (int kt = 0; kt < KT; kt++) {
        int stg = kt & 1;
        if (kt + 1 < KT) {
            loadKV(kt + 1, stg ^ 1);
            asm volatile("cp.async.wait_group 1;" ::: "memory");
        } else {
            asm volatile("cp.async.wait_group 0;" ::: "memory");
        }
        __syncthreads();

        uint32_t Kst = sb + AT_KV0 + stg * AT_STG;
        uint32_t Vst = Kst + 9216;

        float sc[8][4];
        #pragma unroll
        for (int nb = 0; nb < 8; nb++)
            #pragma unroll
            for (int j = 0; j < 4; j++) sc[nb][j] = 0.f;

        int j2 = lane >> 3;
        int rin = lane & 7;
        #pragma unroll
        for (int p = 0; p < 4; p++) {
            #pragma unroll
            for (int kb = 0; kb < 4; kb++) {
                uint32_t addr = Kst + (p * 16 + (j2 >> 1) * 8 + rin) * AT_ROW
                                    + kb * 32 + (j2 & 1) * 16;
                uint32_t b0, b1, b2, b3;
                ldmx4(b0, b1, b2, b3, addr);
                mma16816(sc[2 * p + 0], qf[kb], b0, b1);
                mma16816(sc[2 * p + 1], qf[kb], b2, b3);
            }
        }

        float mx0 = -1e30f, mx1 = -1e30f;
        #pragma unroll
        for (int nb = 0; nb < 8; nb++) {
            mx0 = fmaxf(mx0, fmaxf(sc[nb][0], sc[nb][1]));
            mx1 = fmaxf(mx1, fmaxf(sc[nb][2], sc[nb][3]));
        }
        mx0 = fmaxf(mx0, __shfl_xor_sync(0xffffffffu, mx0, 1));
        mx0 = fmaxf(mx0, __shfl_xor_sync(0xffffffffu, mx0, 2));
        mx1 = fmaxf(mx1, __shfl_xor_sync(0xffffffffu, mx1, 1));
        mx1 = fmaxf(mx1, __shfl_xor_sync(0xffffffffu, mx1, 2));

        float mn0 = fmaxf(m0, mx0), mn1 = fmaxf(m1, mx1);
        float corr0 = __expf(m0 - mn0), corr1 = __expf(m1 - mn1);
        m0 = mn0; m1 = mn1;

        uint32_t pa[8], pb[8];
        float sum0 = 0.f, sum1 = 0.f;
        #pragma unroll
        for (int nb = 0; nb < 8; nb++) {
            float p0 = __expf(sc[nb][0] - mn0);
            float p1 = __expf(sc[nb][1] - mn0);
            float p2 = __expf(sc[nb][2] - mn1);
            float p3 = __expf(sc[nb][3] - mn1);
            sum0 += p0 + p1; sum1 += p2 + p3;
            pa[nb] = pack_bf16(p0, p1);
            pb[nb] = pack_bf16(p2, p3);
        }
        sum0 += __shfl_xor_sync(0xffffffffu, sum0, 1);
        sum0 += __shfl_xor_sync(0xffffffffu, sum0, 2);
        sum1 += __shfl_xor_sync(0xffffffffu, sum1, 1);
        sum1 += __shfl_xor_sync(0xffffffffu, sum1, 2);
        l0 = l0 * corr0 + sum0;
        l1 = l1 * corr1 + sum1;

        #pragma unroll
        for (int nd = 0; nd < 8; nd++) {
            o[nd][0] *= corr0; o[nd][1] *= corr0;
            o[nd][2] *= corr1; o[nd][3] *= corr1;
        }

        #pragma unroll
        for (int kb = 0; kb < 4; kb++) {
            uint32_t a[4] = { pa[2 * kb], pb[2 * kb], pa[2 * kb + 1], pb[2 * kb + 1] };
            #pragma unroll
            for (int v = 0; v < 4; v++) {
                uint32_t addr = Vst + (kb * 16 + (j2 & 1) * 8 + rin) * AT_ROW
                                    + v * 32 + (j2 >> 1) * 16;
                uint32_t b0, b1, b2, b3;
                ldmx4t(b0, b1, b2, b3, addr);
                mma16816(o[2 * v + 0], a, b0, b1);
                mma16816(o[2 * v + 1], a, b2, b3);
            }
        }
        __syncthreads();
    }

    float inv0 = 1.0f / l0, inv1 = 1.0f / l1;
    int rowa = tq0 + r0 + (lane >> 2);
    size_t toka = (size_t)b * NN + rowa;
    size_t tokb = toka + 8;
    int cb = h * DD + (lane & 3) * 2;
    #pragma unroll
    for (int nd = 0; nd < 8; nd++) {
        int d = cb + nd * 8;
        float2 ga = *(const float2*)(gate + toka * CC + d);
        float2 gb = *(const float2*)(gate + tokb * CC + d);
        *(uint32_t*)(outb + toka * CC + d) = pack_bf16(o[nd][0] * inv0 * ga.x,
                                                       o[nd][1] * inv0 * ga.y);
        *(uint32_t*)(outb + tokb * CC + d) = pack_bf16(o[nd][2] * inv1 * gb.x,
                                                       o[nd][3] * inv1 * gb.y);
    }
}

// ---------------------------------------------------------------------------
extern "C" void kernel_launch(void* const* d_in, const int* in_sizes, int n_in,
                              void* d_out, int out_size) {
    const float* x      = (const float*)d_in[0];
    const float* e      = (const float*)d_in[1];
    const float* w_qkv  = (const float*)d_in[2];
    const float* w_s    = (const float*)d_in[3];
    const float* w_gate = (const float*)d_in[4];
    const float* w_proj = (const float*)d_in[5];
    const float* b_proj = (const float*)d_in[6];
    const float* ln1_w  = (const float*)d_in[7];
    const float* ln1_b  = (const float*)d_in[8];
    const float* ln2_w  = (const float*)d_in[9];
    const float* ln2_b  = (const float*)d_in[10];
    const float* ln3_w  = (const float*)d_in[11];
    const float* ln3_b  = (const float*)d_in[12];
    const float* w_fc1  = (const float*)d_in[13];
    const float* b_fc1  = (const float*)d_in[14];
    const float* w_fc2  = (const float*)d_in[15];
    const float* b_fc2  = (const float*)d_in[16];
    float* out = (float*)d_out;

    void* scr_v = nullptr;
    cudaGetSymbolAddress(&scr_v, g_scratch);
    float* scr = (float*)scr_v;
    float*         g_s    = scr + OFF_S;
    float*         g_gate = scr + OFF_GATE;
    float*         g_x1   = scr + OFF_X1;
    __nv_bfloat16* g_xnb  = (__nv_bfloat16*)(scr + OFF_XNB);
    __nv_bfloat16* g_enb  = (__nv_bfloat16*)(scr + OFF_ENB);
    __nv_bfloat16* g_xn3b = (__nv_bfloat16*)(scr + OFF_XN3B);
    __nv_bfloat16* g_agb  = (__nv_bfloat16*)(scr + OFF_AGB);
    __nv_bfloat16* g_hb   = (__nv_bfloat16*)(scr + OFF_HB);
    __nv_bfloat16* wqkvg  = (__nv_bfloat16*)(scr + OFF_WQKVG);
    __nv_bfloat16* wsT    = (__nv_bfloat16*)(scr + OFF_WST);
    __nv_bfloat16* wpT    = (__nv_bfloat16*)(scr + OFF_WPT);
    __nv_bfloat16* wf1T   = (__nv_bfloat16*)(scr + OFF_WF1T);
    __nv_bfloat16* wf2T   = (__nv_bfloat16*)(scr + OFF_WF2T);
    __nv_bfloat16* g_qh   = (__nv_bfloat16*)(scr + OFF_QH);
    __nv_bfloat16* g_kh   = (__nv_bfloat16*)(scr + OFF_KH);
    __nv_bfloat16* g_vh   = (__nv_bfloat16*)(scr + OFF_VH);

    cudaFuncSetAttribute(attn_kernel, cudaFuncAttributeMaxDynamicSharedMemorySize, AT_SMEM);
    cudaFuncSetAttribute(mm2_kernel<0>, cudaFuncAttributeMaxDynamicSharedMemorySize, M2_SMEM);
    cudaFuncSetAttribute(mm2_kernel<1>, cudaFuncAttributeMaxDynamicSharedMemorySize, M2_SMEM);
    cudaFuncSetAttribute(mm2_kernel<2>, cudaFuncAttributeMaxDynamicSharedMemorySize, M2_SMEM);

    // all weight transposes in one launch
    wt_all_kernel<<<3584, dim3(32, 8)>>>(w_qkv, w_gate, w_s, w_proj, w_fc1, w_fc2,
                                         wqkvg, wsT, wpT, wf1T, wf2T);

    // LN1(x) and LN2(e) in one launch
    ln2x_kernel<<<dim3(TT, 2), 128>>>(x, e, ln1_w, ln1_b, ln2_w, ln2_b, g_xnb, g_enb);

    // s = en @ w_s  (fp32, needed by qkvg epilogue)
    mm2_kernel<0><<<dim3(CC / 128, TT / 256), 512, M2_SMEM>>>(
        g_enb, wsT, nullptr, nullptr, nullptr, g_s, nullptr, nullptr, nullptr,
        TT, CC, CC);

    // fused qkv+gate GEMM with per-head scatter epilogue
    mm2_kernel<2><<<dim3(2048 / 128, TT / 256), 512, M2_SMEM>>>(
        g_xnb, wqkvg, nullptr, nullptr, g_s, g_gate, g_qh, g_kh, g_vh,
        TT, 2048, CC);

    attn_kernel<<<dim3(NN / 128, HH, BB), 256, AT_SMEM>>>(g_qh, g_kh, g_vh, g_gate, g_agb);

    // x1 = x + ag @ w_proj + b_proj
    mm2_kernel<0><<<dim3(CC / 128, TT / 256), 512, M2_SMEM>>>(
        g_agb, wpT, b_proj, x, nullptr, g_x1, nullptr, nullptr, nullptr,
        TT, CC, CC);

    ln_kernel<<<TT, 128>>>(g_x1, ln3_w, ln3_b, g_xn3b);

    // h = gelu(xn3 @ w_fc1 + b_fc1) -> bf16
    mm2_kernel<1><<<dim3(FF / 128, TT / 256), 512, M2_SMEM>>>(
        g_xn3b, wf1T, b_fc1, nullptr, nullptr, nullptr, g_hb, nullptr, nullptr,
        TT, FF, CC);

    // out = x1 + h @ w_fc2 + b_fc2
    mm2_kernel<0><<<dim3(CC / 128, TT / 256), 512, M2_SMEM>>>(
        g_hb, wf2T, b_fc2, g_x1, nullptr, out, nullptr, nullptr, nullptr,
        TT, CC, FF);
}

// round 12
// speedup vs baseline: 7.4293x; 1.0972x over previous
#include <cuda_runtime.h>
#include <cuda_bf16.h>
#include <math.h>
#include <cstdint>

// Problem constants
#define BB 4
#define NN 2048
#define CC 512
#define HH 8
#define DD 64
#define TT (BB*NN)          // 8192 tokens
#define FF 2048             // d_ff

// ---------------------------------------------------------------------------
// Scratch layout (float units)
#define OFF_S     0ull          // fp32 [TT, C]
#define OFF_GATE  4194304ull    // fp32 [TT, C]
#define OFF_X1    8388608ull    // fp32 [TT, C]
#define OFF_XNB   12582912ull   // bf16 [TT, C]
#define OFF_ENB   14680064ull   // bf16 [TT, C]
#define OFF_XN3B  16777216ull   // bf16 [TT, C]
#define OFF_AGB   18874368ull   // bf16 [TT, C]
#define OFF_HB    20971520ull   // bf16 [TT, FF]
#define OFF_WQKVG 29360128ull   // bf16 [2048, 512]  (rows: wqkvT 0..1535, wgT 1536..2047)
#define OFF_WST   29884416ull   // bf16 [C, C]
#define OFF_WPT   30015488ull   // bf16 [C, C]
#define OFF_WF1T  30146560ull   // bf16 [FF, C]
#define OFF_WF2T  30670848ull   // bf16 [C, FF]
#define OFF_QH    31195136ull   // bf16 [B*H, N, 64]
#define OFF_KH    33292288ull   // bf16 [B*H, N, 64]
#define OFF_VH    35389440ull   // bf16 [B*H, N, 64]
#define SCRATCH_FLOATS 37486592ull

__device__ float g_scratch[SCRATCH_FLOATS];

// ---------------------------------------------------------------------------
__device__ __forceinline__ uint32_t smem_u32(const void* p) {
    uint32_t a;
    asm("{ .reg .u64 t; cvta.to.shared.u64 t, %1; cvt.u32.u64 %0, t; }" : "=r"(a) : "l"(p));
    return a;
}
__device__ __forceinline__ void cp_async16(uint32_t saddr, const void* gaddr) {
    asm volatile("cp.async.cg.shared.global [%0], [%1], 16;" :: "r"(saddr), "l"(gaddr) : "memory");
}
__device__ __forceinline__ void cp_commit() {
    asm volatile("cp.async.commit_group;" ::: "memory");
}
__device__ __forceinline__ void ldmx4(uint32_t& r0, uint32_t& r1, uint32_t& r2, uint32_t& r3,
                                      uint32_t addr) {
    asm volatile("ldmatrix.sync.aligned.m8n8.x4.shared.b16 {%0,%1,%2,%3}, [%4];"
                 : "=r"(r0), "=r"(r1), "=r"(r2), "=r"(r3) : "r"(addr));
}
__device__ __forceinline__ void ldmx4t(uint32_t& r0, uint32_t& r1, uint32_t& r2, uint32_t& r3,
                                       uint32_t addr) {
    asm volatile("ldmatrix.sync.aligned.m8n8.x4.trans.shared.b16 {%0,%1,%2,%3}, [%4];"
                 : "=r"(r0), "=r"(r1), "=r"(r2), "=r"(r3) : "r"(addr));
}
__device__ __forceinline__ void mma16816(float* c, const uint32_t* a, uint32_t b0, uint32_t b1) {
    asm volatile(
        "mma.sync.aligned.m16n8k16.row.col.f32.bf16.bf16.f32 "
        "{%0,%1,%2,%3}, {%4,%5,%6,%7}, {%8,%9}, {%0,%1,%2,%3};"
        : "+f"(c[0]), "+f"(c[1]), "+f"(c[2]), "+f"(c[3])
        : "r"(a[0]), "r"(a[1]), "r"(a[2]), "r"(a[3]), "r"(b0), "r"(b1));
}
__device__ __forceinline__ uint32_t pack_bf16(float a, float b) {
    __nv_bfloat162 p = __floats2bfloat162_rn(a, b);
    return *(uint32_t*)&p;
}

// ---------------------------------------------------------------------------
// Fused LayerNorm for LN1(x) and LN2(e): blockIdx.y selects.
__global__ void ln2x_kernel(const float* __restrict__ x, const float* __restrict__ e,
                            const float* __restrict__ w1, const float* __restrict__ b1,
                            const float* __restrict__ w2, const float* __restrict__ b2,
                            __nv_bfloat16* __restrict__ y1, __nv_bfloat16* __restrict__ y2) {
    int row = blockIdx.x;
    int which = blockIdx.y;
    const float* src = which ? e : x;
    const float* w   = which ? w2 : w1;
    const float* b   = which ? b2 : b1;
    __nv_bfloat16* y = which ? y2 : y1;
    int tid = threadIdx.x;
    const float4* xr = (const float4*)(src + (size_t)row * CC);
    float4 v = xr[tid];
    float s  = v.x + v.y + v.z + v.w;
    float ss = v.x*v.x + v.y*v.y + v.z*v.z + v.w*v.w;
    #pragma unroll
    for (int off = 16; off; off >>= 1) {
        s  += __shfl_xor_sync(0xffffffffu, s,  off);
        ss += __shfl_xor_sync(0xffffffffu, ss, off);
    }
    __shared__ float sm[4], sm2[4];
    int warp = tid >> 5, lane = tid & 31;
    if (lane == 0) { sm[warp] = s; sm2[warp] = ss; }
    __syncthreads();
    float tot  = sm[0] + sm[1] + sm[2] + sm[3];
    float tot2 = sm2[0] + sm2[1] + sm2[2] + sm2[3];
    float mu   = tot * (1.0f / CC);
    float var  = tot2 * (1.0f / CC) - mu * mu;
    float rstd = rsqrtf(var + 1e-5f);
    float4 wv = ((const float4*)w)[tid];
    float4 bv = ((const float4*)b)[tid];
    uint2 o;
    o.x = pack_bf16((v.x - mu) * rstd * wv.x + bv.x, (v.y - mu) * rstd * wv.y + bv.y);
    o.y = pack_bf16((v.z - mu) * rstd * wv.z + bv.z, (v.w - mu) * rstd * wv.w + bv.w);
    ((uint2*)(y + (size_t)row * CC))[tid] = o;
}

// Single-tensor LN (for LN3)
__global__ void ln_kernel(const float* __restrict__ x,
                          const float* __restrict__ w,
                          const float* __restrict__ b,
                          __nv_bfloat16* __restrict__ y) {
    int row = blockIdx.x;
    int tid = threadIdx.x;
    const float4* xr = (const float4*)(x + (size_t)row * CC);
    float4 v = xr[tid];
    float s  = v.x + v.y + v.z + v.w;
    float ss = v.x*v.x + v.y*v.y + v.z*v.z + v.w*v.w;
    #pragma unroll
    for (int off = 16; off; off >>= 1) {
        s  += __shfl_xor_sync(0xffffffffu, s,  off);
        ss += __shfl_xor_sync(0xffffffffu, ss, off);
    }
    __shared__ float sm[4], sm2[4];
    int warp = tid >> 5, lane = tid & 31;
    if (lane == 0) { sm[warp] = s; sm2[warp] = ss; }
    __syncthreads();
    float tot  = sm[0] + sm[1] + sm[2] + sm[3];
    float tot2 = sm2[0] + sm2[1] + sm2[2] + sm2[3];
    float mu   = tot * (1.0f / CC);
    float var  = tot2 * (1.0f / CC) - mu * mu;
    float rstd = rsqrtf(var + 1e-5f);
    float4 wv = ((const float4*)w)[tid];
    float4 bv = ((const float4*)b)[tid];
    uint2 o;
    o.x = pack_bf16((v.x - mu) * rstd * wv.x + bv.x, (v.y - mu) * rstd * wv.y + bv.y);
    o.y = pack_bf16((v.z - mu) * rstd * wv.z + bv.z, (v.w - mu) * rstd * wv.w + bv.w);
    ((uint2*)(y + (size_t)row * CC))[tid] = o;
}

// ---------------------------------------------------------------------------
// Uber weight-transpose: all 6 weights in one launch. Tile id -> weight.
__global__ void wt_all_kernel(
    const float* __restrict__ w_qkv, const float* __restrict__ w_gate,
    const float* __restrict__ w_s,   const float* __restrict__ w_proj,
    const float* __restrict__ w_fc1, const float* __restrict__ w_fc2,
    __nv_bfloat16* __restrict__ wqkvg, __nv_bfloat16* __restrict__ wsT,
    __nv_bfloat16* __restrict__ wpT,   __nv_bfloat16* __restrict__ wf1T,
    __nv_bfloat16* __restrict__ wf2T)
{
    __shared__ float t[32][33];
    int tb = blockIdx.x;
    const float* W; __nv_bfloat16* WT; int K, N, ntx, loc;
    if (tb < 768)       { W = w_qkv;  WT = wqkvg;                       K = 512;  N = 1536; ntx = 48; loc = tb; }
    else if (tb < 1024) { W = w_gate; WT = wqkvg + (size_t)1536 * 512;  K = 512;  N = 512;  ntx = 16; loc = tb - 768; }
    else if (tb < 1280) { W = w_s;    WT = wsT;                         K = 512;  N = 512;  ntx = 16; loc = tb - 1024; }
    else if (tb < 1536) { W = w_proj; WT = wpT;                         K = 512;  N = 512;  ntx = 16; loc = tb - 1280; }
    else if (tb < 2560) { W = w_fc1;  WT = wf1T;                        K = 512;  N = 2048; ntx = 64; loc = tb - 1536; }
    else                { W = w_fc2;  WT = wf2T;                        K = 2048; N = 512;  ntx = 16; loc = tb - 2560; }
    int n0 = (loc % ntx) * 32, k0 = (loc / ntx) * 32;
    int tx = threadIdx.x, ty = threadIdx.y;   // 32 x 8
    #pragma unroll
    for (int i = 0; i < 32; i += 8)
        t[ty + i][tx] = W[(size_t)(k0 + ty + i) * N + n0 + tx];
    __syncthreads();
    #pragma unroll
    for (int i = 0; i < 32; i += 8)
        WT[(size_t)(n0 + ty + i) * K + k0 + tx] = __float2bfloat16(t[tx][ty + i]);
}

// ---------------------------------------------------------------------------
// mm2: HMMA bf16 GEMM, 128x128 CTA tile, 256 threads (8 warps, 2x4, 64x32
// warp tiles), BK=64 (128B rows, stride 144), 3-stage cp.async, 2 CTAs/SM.
// MODE 0: fp32 out = A@Bt^T (+bias) (+res)
// MODE 1: bf16 out = gelu(A@Bt^T + bias)
// MODE 2: qkvg epilogue (N=2048): seg0 q*0.125->qh, seg1 k+s->kh, seg2 v->vh,
//         seg3 gate fp32. Per-head layouts.
#define M2_ROW  144
#define M2_B    18432           // A: 128 rows; B at row 128
#define M2_STG  36864           // 256 * 144
#define M2_NSTG 3
#define M2_SMEM (M2_NSTG * M2_STG)   // 110592

template<int MODE>
__global__ void __launch_bounds__(256, 2) mm2_kernel(
    const __nv_bfloat16* __restrict__ A,   // [M,K]
    const __nv_bfloat16* __restrict__ Bt,  // [N,K]
    const float* __restrict__ bias,
    const float* __restrict__ res,
    const float* __restrict__ sextra,      // MODE 2: s [TT, 512]
    float* __restrict__ outf,              // MODE 0 / MODE 2 gate
    __nv_bfloat16* __restrict__ outb0,     // MODE 1 out / MODE 2 qh
    __nv_bfloat16* __restrict__ outb1,     // MODE 2 kh
    __nv_bfloat16* __restrict__ outb2,     // MODE 2 vh
    int M, int N, int K)
{
    extern __shared__ __align__(16) char smem[];
    uint32_t sb = smem_u32(smem);

    int tid = threadIdx.x, wid = tid >> 5, lane = tid & 31;
    int m0 = blockIdx.y * 128, n0 = blockIdx.x * 128;
    int wm = wid & 1, wn = wid >> 1;        // 2 x 4 warps, 64x32 each

    const char* Abase = (const char*)A;
    const char* Bbase = (const char*)Bt;
    size_t rstride = (size_t)K * 2;
    int KC = K >> 6;   // BK = 64

    auto load_tile = [&](int kc, int stg) {
        uint32_t base = sb + stg * M2_STG;
        size_t koff = (size_t)kc * 128;
        #pragma unroll
        for (int i = 0; i < 8; i++) {
            int idx = i * 256 + tid;         // 0..2047
            int row = idx >> 3;              // 0..255
            int c = (idx & 7) * 16;
            const char* g = (row < 128)
                ? Abase + (size_t)(m0 + row) * rstride + koff + c
                : Bbase + (size_t)(n0 + row - 128) * rstride + koff + c;
            cp_async16(base + row * M2_ROW + c, g);
        }
        cp_commit();
    };

    float acc[4][4][4];
    #pragma unroll
    for (int mi = 0; mi < 4; mi++)
        #pragma unroll
        for (int nb = 0; nb < 4; nb++)
            #pragma unroll
            for (int j = 0; j < 4; j++) acc[mi][nb][j] = 0.f;

    load_tile(0, 0);
    load_tile(1, 1);

    uint32_t lrow16 = (lane & 15);
    uint32_t lkhalf = (lane >> 4) * 16;

    for (int kc = 0; kc < KC; kc++) {
        if (kc < KC - 1) asm volatile("cp.async.wait_group 1;" ::: "memory");
        else             asm volatile("cp.async.wait_group 0;" ::: "memory");
        __syncthreads();

        if (kc + 2 < KC) load_tile(kc + 2, (kc + 2) % M2_NSTG);

        int stg = kc % M2_NSTG;
        uint32_t sA = sb + stg * M2_STG + (wm * 64 + lrow16) * M2_ROW + lkhalf;
        uint32_t sB = sb + stg * M2_STG + M2_B + (wn * 32 + lrow16) * M2_ROW + lkhalf;

        #pragma unroll
        for (int ks = 0; ks < 4; ks++) {
            uint32_t koff = ks * 32;
            uint32_t a[4][4];
            #pragma unroll
            for (int mi = 0; mi < 4; mi++)
                ldmx4(a[mi][0], a[mi][1], a[mi][2], a[mi][3],
                      sA + mi * 16 * M2_ROW + koff);
            uint32_t b[2][4];
            #pragma unroll
            for (int nb = 0; nb < 2; nb++)
                ldmx4(b[nb][0], b[nb][1], b[nb][2], b[nb][3],
                      sB + nb * 16 * M2_ROW + koff);
            #pragma unroll
            for (int mi = 0; mi < 4; mi++)
                #pragma unroll
                for (int nb = 0; nb < 2; nb++) {
                    mma16816(acc[mi][nb * 2 + 0], a[mi], b[nb][0], b[nb][2]);
                    mma16816(acc[mi][nb * 2 + 1], a[mi], b[nb][1], b[nb][3]);
                }
        }
        __syncthreads();
    }

    // ---- epilogue ----
    int mbase = m0 + wm * 64 + (lane >> 2);
    int nbase = n0 + wn * 32 + (lane & 3) * 2;
    int seg = nbase >> 9;          // uniform per warp (MODE 2)

    #pragma unroll
    for (int mi = 0; mi < 4; mi++) {
        #pragma unroll
        for (int nb = 0; nb < 4; nb++) {
            int n = nbase + nb * 8;
            #pragma unroll
            for (int half = 0; half < 2; half++) {
                int m = mbase + mi * 16 + half * 8;
                float v0 = acc[mi][nb][half * 2 + 0];
                float v1 = acc[mi][nb][half * 2 + 1];
                if (MODE == 0) {
                    if (bias) { v0 += bias[n]; v1 += bias[n + 1]; }
                    if (res) {
                        const float* rp = res + (size_t)m * N + n;
                        v0 += rp[0]; v1 += rp[1];
                    }
                    *(float2*)(outf + (size_t)m * N + n) = make_float2(v0, v1);
                } else if (MODE == 1) {
                    v0 += bias[n]; v1 += bias[n + 1];
                    v0 = 0.5f * v0 * (1.0f + erff(v0 * 0.70710678118654752f));
                    v1 = 0.5f * v1 * (1.0f + erff(v1 * 0.70710678118654752f));
                    *(uint32_t*)(outb0 + (size_t)m * N + n) = pack_bf16(v0, v1);
                } else {
                    int c = n & 511;
                    int bidx = m >> 11, nloc = m & (NN - 1);
                    if (seg == 3) {
                        *(float2*)(outf + (size_t)m * CC + c) = make_float2(v0, v1);
                    } else {
                        int h = c >> 6, d = c & 63;
                        size_t ph = (((size_t)(bidx * HH + h) * NN + nloc) << 6) + d;
                        if (seg == 0) {
                            *(uint32_t*)(outb0 + ph) = pack_bf16(v0 * 0.125f, v1 * 0.125f);
                        } else if (seg == 1) {
                            float2 sv = *(const float2*)(sextra + (size_t)m * CC + c);
                            *(uint32_t*)(outb1 + ph) = pack_bf16(v0 + sv.x, v1 + sv.y);
                        } else {
                            *(uint32_t*)(outb2 + ph) = pack_bf16(v0, v1);
                        }
                    }
                }
            }
        }
    }
}

// ---------------------------------------------------------------------------
// bf16 HMMA flash attention, fused gate-multiply epilogue.
#define AT_QOFF 0
#define AT_ROW  144
#define AT_KV0  18432
#define AT_STG  18432
#define AT_SMEM (18432 + 2 * 18432)

__global__ void __launch_bounds__(256) attn_kernel(
    const __nv_bfloat16* __restrict__ qh,
    const __nv_bfloat16* __restrict__ kh,
    const __nv_bfloat16* __restrict__ vh,
    const float* __restrict__ gate,
    __nv_bfloat16* __restrict__ outb)
{
    extern __shared__ char smem[];
    uint32_t sb = smem_u32(smem);
    int tid = threadIdx.x, wid = tid >> 5, lane = tid & 31;
    int qt = blockIdx.x, h = blockIdx.y, b = blockIdx.z;
    int bh = b * HH + h;
    int tq0 = qt * 128;

    const char* Qg = (const char*)(qh + (((size_t)bh * NN + tq0) << 6));
    const char* Kg = (const char*)(kh + ((size_t)bh * NN << 6));
    const char* Vg = (const char*)(vh + ((size_t)bh * NN << 6));

    for (int i = tid; i < 1024; i += 256) {
        int r = i >> 3, c = (i & 7) * 16;
        cp_async16(sb + AT_QOFF + r * AT_ROW + c, Qg + (size_t)r * 128 + c);
    }
    cp_commit();

    auto loadKV = [&](int kt, int stg) {
        const char* K0 = Kg + ((size_t)kt << 13);
        const char* V0 = Vg + ((size_t)kt << 13);
        uint32_t ks = sb + AT_KV0 + stg * AT_STG;
        for (int i = tid; i < 512; i += 256) {
            int r = i >> 3, c = (i & 7) * 16;
            cp_async16(ks + r * AT_ROW + c, K0 + (size_t)r * 128 + c);
            cp_async16(ks + 9216 + r * AT_ROW + c, V0 + (size_t)r * 128 + c);
        }
        cp_commit();
    };

    loadKV(0, 0);
    asm volatile("cp.async.wait_group 0;" ::: "memory");
    __syncthreads();

    int r0 = wid * 16;
    uint32_t qf[4][4];
    {
        uint32_t base = sb + AT_QOFF + (r0 + (lane & 15)) * AT_ROW + (lane >> 4) * 16;
        #pragma unroll
        for (int kb = 0; kb < 4; kb++)
            ldmx4(qf[kb][0], qf[kb][1], qf[kb][2], qf[kb][3], base + kb * 32);
    }

    float o[8][4];
    #pragma unroll
    for (int nd = 0; nd < 8; nd++)
        #pragma unroll
        for (int j = 0; j < 4; j++) o[nd][j] = 0.f;
    float m0 = -1e30f, m1 = -1e30f, l0 = 0.f, l1 = 0.f;

    const int KT = NN / 64;
    for (int kt = 0; kt < KT; kt++) {
        int stg = kt & 1;
        if (kt + 1 < KT) {
            loadKV(kt + 1, stg ^ 1);
            asm volatile("cp.async.wait_group 1;" ::: "memory");
        } else {
            asm volatile("cp.async.wait_group 0;" ::: "memory");
        }
        __syncthreads();

        uint32_t Kst = sb + AT_KV0 + stg * AT_STG;
        uint32_t Vst = Kst + 9216;

        float sc[8][4];
        #pragma unroll
        for (int nb = 0; nb < 8; nb++)
            #pragma unroll
            for (int j = 0; j < 4; j++) sc[nb][j] = 0.f;

        int j2 = lane >> 3;
        int rin = lane & 7;
        #pragma unroll
        for (int p = 0; p < 4; p++) {
            #pragma unroll
            for (int kb = 0; kb < 4; kb++) {
                uint32_t addr = Kst + (p * 16 + (j2 >> 1) * 8 + rin) * AT_ROW
                                    + kb * 32 + (j2 & 1) * 16;
                uint32_t b0, b1, b2, b3;
                ldmx4(b0, b1, b2, b3, addr);
                mma16816(sc[2 * p + 0], qf[kb], b0, b1);
                mma16816(sc[2 * p + 1], qf[kb], b2, b3);
            }
        }

        float mx0 = -1e30f, mx1 = -1e30f;
        #pragma unroll
        for (int nb = 0; nb < 8; nb++) {
            mx0 = fmaxf(mx0, fmaxf(sc[nb][0], sc[nb][1]));
            mx1 = fmaxf(mx1, fmaxf(sc[nb][2], sc[nb][3]));
        }
        mx0 = fmaxf(mx0, __shfl_xor_sync(0xffffffffu, mx0, 1));
        mx0 = fmaxf(mx0, __shfl_xor_sync(0xffffffffu, mx0, 2));
        mx1 = fmaxf(mx1, __shfl_xor_sync(0xffffffffu, mx1, 1));
        mx1 = fmaxf(mx1, __shfl_xor_sync(0xffffffffu, mx1, 2));

        float mn0 = fmaxf(m0, mx0), mn1 = fmaxf(m1, mx1);
        float corr0 = __expf(m0 - mn0), corr1 = __expf(m1 - mn1);
        m0 = mn0; m1 = mn1;

        uint32_t pa[8], pb[8];
        float sum0 = 0.f, sum1 = 0.f;
        #pragma unroll
        for (int nb = 0; nb < 8; nb++) {
            float p0 = __expf(sc[nb][0] - mn0);
            float p1 = __expf(sc[nb][1] - mn0);
            float p2 = __expf(sc[nb][2] - mn1);
            float p3 = __expf(sc[nb][3] - mn1);
            sum0 += p0 + p1; sum1 += p2 + p3;
            pa[nb] = pack_bf16(p0, p1);
            pb[nb] = pack_bf16(p2, p3);
        }
        sum0 += __shfl_xor_sync(0xffffffffu, sum0, 1);
        sum0 += __shfl_xor_sync(0xffffffffu, sum0, 2);
        sum1 += __shfl_xor_sync(0xffffffffu, sum1, 1);
        sum1 += __shfl_xor_sync(0xffffffffu, sum1, 2);
        l0 = l0 * corr0 + sum0;
        l1 = l1 * corr1 + sum1;

        #pragma unroll
        for (int nd = 0; nd < 8; nd++) {
            o[nd][0] *= corr0; o[nd][1] *= corr0;
            o[nd][2] *= corr1; o[nd][3] *= corr1;
        }

        #pragma unroll
        for (int kb = 0; kb < 4; kb++) {
            uint32_t a[4] = { pa[2 * kb], pb[2 * kb], pa[2 * kb + 1], pb[2 * kb + 1] };
            #pragma unroll
            for (int v = 0; v < 4; v++) {
                uint32_t addr = Vst + (kb * 16 + (j2 & 1) * 8 + rin) * AT_ROW
                                    + v * 32 + (j2 >> 1) * 16;
                uint32_t b0, b1, b2, b3;
                ldmx4t(b0, b1, b2, b3, addr);
                mma16816(o[2 * v + 0], a, b0, b1);
                mma16816(o[2 * v + 1], a, b2, b3);
            }
        }
        __syncthreads();
    }

    float inv0 = 1.0f / l0, inv1 = 1.0f / l1;
    int rowa = tq0 + r0 + (lane >> 2);
    size_t toka = (size_t)b * NN + rowa;
    size_t tokb = toka + 8;
    int cb = h * DD + (lane & 3) * 2;
    #pragma unroll
    for (int nd = 0; nd < 8; nd++) {
        int d = cb + nd * 8;
        float2 ga = *(const float2*)(gate + toka * CC + d);
        float2 gb = *(const float2*)(gate + tokb * CC + d);
        *(uint32_t*)(outb + toka * CC + d) = pack_bf16(o[nd][0] * inv0 * ga.x,
                                                       o[nd][1] * inv0 * ga.y);
        *(uint32_t*)(outb + tokb * CC + d) = pack_bf16(o[nd][2] * inv1 * gb.x,
                                                       o[nd][3] * inv1 * gb.y);
    }
}

// ---------------------------------------------------------------------------
extern "C" void kernel_launch(void* const* d_in, const int* in_sizes, int n_in,
                              void* d_out, int out_size) {
    const float* x      = (const float*)d_in[0];
    const float* e      = (const float*)d_in[1];
    const float* w_qkv  = (const float*)d_in[2];
    const float* w_s    = (const float*)d_in[3];
    const float* w_gate = (const float*)d_in[4];
    const float* w_proj = (const float*)d_in[5];
    const float* b_proj = (const float*)d_in[6];
    const float* ln1_w  = (const float*)d_in[7];
    const float* ln1_b  = (const float*)d_in[8];
    const float* ln2_w  = (const float*)d_in[9];
    const float* ln2_b  = (const float*)d_in[10];
    const float* ln3_w  = (const float*)d_in[11];
    const float* ln3_b  = (const float*)d_in[12];
    const float* w_fc1  = (const float*)d_in[13];
    const float* b_fc1  = (const float*)d_in[14];
    const float* w_fc2  = (const float*)d_in[15];
    const float* b_fc2  = (const float*)d_in[16];
    float* out = (float*)d_out;

    void* scr_v = nullptr;
    cudaGetSymbolAddress(&scr_v, g_scratch);
    float* scr = (float*)scr_v;
    float*         g_s    = scr + OFF_S;
    float*         g_gate = scr + OFF_GATE;
    float*         g_x1   = scr + OFF_X1;
    __nv_bfloat16* g_xnb  = (__nv_bfloat16*)(scr + OFF_XNB);
    __nv_bfloat16* g_enb  = (__nv_bfloat16*)(scr + OFF_ENB);
    __nv_bfloat16* g_xn3b = (__nv_bfloat16*)(scr + OFF_XN3B);
    __nv_bfloat16* g_agb  = (__nv_bfloat16*)(scr + OFF_AGB);
    __nv_bfloat16* g_hb   = (__nv_bfloat16*)(scr + OFF_HB);
    __nv_bfloat16* wqkvg  = (__nv_bfloat16*)(scr + OFF_WQKVG);
    __nv_bfloat16* wsT    = (__nv_bfloat16*)(scr + OFF_WST);
    __nv_bfloat16* wpT    = (__nv_bfloat16*)(scr + OFF_WPT);
    __nv_bfloat16* wf1T   = (__nv_bfloat16*)(scr + OFF_WF1T);
    __nv_bfloat16* wf2T   = (__nv_bfloat16*)(scr + OFF_WF2T);
    __nv_bfloat16* g_qh   = (__nv_bfloat16*)(scr + OFF_QH);
    __nv_bfloat16* g_kh   = (__nv_bfloat16*)(scr + OFF_KH);
    __nv_bfloat16* g_vh   = (__nv_bfloat16*)(scr + OFF_VH);

    cudaFuncSetAttribute(attn_kernel, cudaFuncAttributeMaxDynamicSharedMemorySize, AT_SMEM);
    cudaFuncSetAttribute(mm2_kernel<0>, cudaFuncAttributeMaxDynamicSharedMemorySize, M2_SMEM);
    cudaFuncSetAttribute(mm2_kernel<1>, cudaFuncAttributeMaxDynamicSharedMemorySize, M2_SMEM);
    cudaFuncSetAttribute(mm2_kernel<2>, cudaFuncAttributeMaxDynamicSharedMemorySize, M2_SMEM);

    // all weight transposes in one launch
    wt_all_kernel<<<3584, dim3(32, 8)>>>(w_qkv, w_gate, w_s, w_proj, w_fc1, w_fc2,
                                         wqkvg, wsT, wpT, wf1T, wf2T);

    // LN1(x) and LN2(e) in one launch
    ln2x_kernel<<<dim3(TT, 2), 128>>>(x, e, ln1_w, ln1_b, ln2_w, ln2_b, g_xnb, g_enb);

    // s = en @ w_s  (fp32, needed by qkvg epilogue)
    mm2_kernel<0><<<dim3(CC / 128, TT / 128), 256, M2_SMEM>>>(
        g_enb, wsT, nullptr, nullptr, nullptr, g_s, nullptr, nullptr, nullptr,
        TT, CC, CC);

    // fused qkv+gate GEMM with per-head scatter epilogue
    mm2_kernel<2><<<dim3(2048 / 128, TT / 128), 256, M2_SMEM>>>(
        g_xnb, wqkvg, nullptr, nullptr, g_s, g_gate, g_qh, g_kh, g_vh,
        TT, 2048, CC);

    attn_kernel<<<dim3(NN / 128, HH, BB), 256, AT_SMEM>>>(g_qh, g_kh, g_vh, g_gate, g_agb);

    // x1 = x + ag @ w_proj + b_proj
    mm2_kernel<0><<<dim3(CC / 128, TT / 128), 256, M2_SMEM>>>(
        g_agb, wpT, b_proj, x, nullptr, g_x1, nullptr, nullptr, nullptr,
        TT, CC, CC);

    ln_kernel<<<TT, 128>>>(g_x1, ln3_w, ln3_b, g_xn3b);

    // h = gelu(xn3 @ w_fc1 + b_fc1) -> bf16
    mm2_kernel<1><<<dim3(FF / 128, TT / 128), 256, M2_SMEM>>>(
        g_xn3b, wf1T, b_fc1, nullptr, nullptr, nullptr, g_hb, nullptr, nullptr,
        TT, FF, CC);

    // out = x1 + h @ w_fc2 + b_fc2
    mm2_kernel<0><<<dim3(CC / 128, TT / 128), 256, M2_SMEM>>>(
        g_hb, wf2T, b_fc2, g_x1, nullptr, out, nullptr, nullptr, nullptr,
        TT, CC, FF);
}